// round 3
// baseline (speedup 1.0000x reference)
#include <cuda_runtime.h>

#define NN 50000
#define EE 800000
#define HD 256
#define TIL 64      // rows per GEMM tile
#define KC  32      // k-chunk staged in smem
#define AST 66      // As_t row stride (floats), even for float2 loads
#define NL  3

// ---------------- scratch (device globals; no allocation allowed) ----------
__device__ float g_h[NN * HD];          // node features per layer
__device__ float g_A[NN * 512];         // [A_src | A_dst] per node
__device__ float g_agg[NN * HD];        // segment sum
__device__ float g_Trel[8 * HD];        // rel contribution + e1_b
__device__ float g_roleS[8 * HD];
__device__ float g_roleD[8 * HD];
__device__ float g_colS[3 * HD];
__device__ float g_colD[3 * HD];
__device__ float g_roleN[8 * HD];       // includes n1_b
__device__ float g_colN[3 * HD];

// ---------------- helpers ---------------------------------------------------
__device__ __forceinline__ float silu_f(float x) {
    return __fdividef(x, 1.0f + __expf(-x));
}

__device__ __forceinline__ unsigned long long fma2(unsigned long long a,
                                                   unsigned long long b,
                                                   unsigned long long c) {
    unsigned long long d;
    asm("fma.rn.f32x2 %0, %1, %2, %3;" : "=l"(d) : "l"(a), "l"(b), "l"(c));
    return d;
}
__device__ __forceinline__ unsigned long long pack2(float lo, float hi) {
    unsigned long long d;
    asm("mov.b64 %0, {%1,%2};" : "=l"(d) : "f"(lo), "f"(hi));
    return d;
}
__device__ __forceinline__ float2 unpack2(unsigned long long v) {
    float2 r;
    asm("mov.b64 {%0,%1}, %2;" : "=f"(r.x), "=f"(r.y) : "l"(v));
    return r;
}

// stage KC rows of W[k][0..255] into smem
__device__ __forceinline__ void load_w_chunk(float* sW, const float* __restrict__ gW,
                                             int kbase, int tid) {
    const float4* src = (const float4*)(gW + (size_t)kbase * HD);
    float4* dst = (float4*)sW;
#pragma unroll
    for (int i = 0; i < (KC * HD / 4) / 256; i++)
        dst[tid + i * 256] = __ldg(src + tid + i * 256);
}

// C[row][c] += sum_k As_t[k][row] * W[k][c], rows paired in f32x2
__device__ __forceinline__ void gemm_chunk(const float* __restrict__ sA,
                                           const float* __restrict__ sW,
                                           int kbase, int r0, int c0,
                                           unsigned long long (&acc)[4][8]) {
#pragma unroll 8
    for (int kk = 0; kk < KC; kk++) {
        const float* ap = sA + (kbase + kk) * AST + r0;
        unsigned long long a0 = *(const unsigned long long*)(ap + 0);
        unsigned long long a1 = *(const unsigned long long*)(ap + 2);
        unsigned long long a2 = *(const unsigned long long*)(ap + 4);
        unsigned long long a3 = *(const unsigned long long*)(ap + 6);
        float4 wa = *(const float4*)(sW + kk * HD + c0);
        float4 wb = *(const float4*)(sW + kk * HD + c0 + 4);
        unsigned long long w2[8];
        w2[0] = pack2(wa.x, wa.x); w2[1] = pack2(wa.y, wa.y);
        w2[2] = pack2(wa.z, wa.z); w2[3] = pack2(wa.w, wa.w);
        w2[4] = pack2(wb.x, wb.x); w2[5] = pack2(wb.y, wb.y);
        w2[6] = pack2(wb.z, wb.z); w2[7] = pack2(wb.w, wb.w);
#pragma unroll
        for (int j = 0; j < 8; j++) {
            acc[0][j] = fma2(a0, w2[j], acc[0][j]);
            acc[1][j] = fma2(a1, w2[j], acc[1][j]);
            acc[2][j] = fma2(a2, w2[j], acc[2][j]);
            acc[3][j] = fma2(a3, w2[j], acc[3][j]);
        }
    }
}

// ---------------- kernels ---------------------------------------------------

// input projection: h = [scalars(16), col_emb(8), role_emb(8)] @ in_w + in_b
__global__ void k_input(const float* __restrict__ sc, const int* __restrict__ colr,
                        const int* __restrict__ role, const float* __restrict__ cemb,
                        const float* __restrict__ remb, const float* __restrict__ inw,
                        const float* __restrict__ inb) {
    __shared__ float xin[32];
    int n = blockIdx.x;
    int tid = threadIdx.x;
    if (tid < 16) xin[tid] = sc[n * 16 + tid];
    else if (tid < 24) xin[tid] = cemb[colr[n] * 8 + (tid - 16)];
    else if (tid < 32) xin[tid] = remb[role[n] * 8 + (tid - 24)];
    __syncthreads();
    float a = inb[tid];
#pragma unroll
    for (int k = 0; k < 32; k++) a += xin[k] * inw[k * HD + tid];
    g_h[n * HD + tid] = a;
}

// small per-layer lookup tables (rel/role/col contributions through e1_w / n1_w)
__global__ void k_tables(int l, const float* __restrict__ rel_embs,
                         const float* __restrict__ role_embs,
                         const float* __restrict__ col_embs,
                         const float* __restrict__ e1w, const float* __restrict__ e1b,
                         const float* __restrict__ n1w, const float* __restrict__ n1b) {
    int b = blockIdx.x, c = threadIdx.x;
    const float* e1 = e1w + (size_t)l * 560 * HD;
    const float* n1 = n1w + (size_t)l * 528 * HD;
    if (b < 8) {
        float a = e1b[l * HD + c];
        const float* em = rel_embs + (l * 8 + b) * 16;
        const float* w = e1 + 512 * HD + c;
#pragma unroll
        for (int k = 0; k < 16; k++) a += em[k] * w[k * HD];
        g_Trel[b * HD + c] = a;
    } else if (b < 16) {
        int r = b - 8; float a = 0.f;
        const float* em = role_embs + (l * 8 + r) * 8;
        const float* w = e1 + 528 * HD + c;
#pragma unroll
        for (int k = 0; k < 8; k++) a += em[k] * w[k * HD];
        g_roleS[r * HD + c] = a;
    } else if (b < 24) {
        int r = b - 16; float a = 0.f;
        const float* em = role_embs + (l * 8 + r) * 8;
        const float* w = e1 + 536 * HD + c;
#pragma unroll
        for (int k = 0; k < 8; k++) a += em[k] * w[k * HD];
        g_roleD[r * HD + c] = a;
    } else if (b < 27) {
        int g = b - 24; float a = 0.f;
        const float* em = col_embs + (l * 3 + g) * 8;
        const float* w = e1 + 544 * HD + c;
#pragma unroll
        for (int k = 0; k < 8; k++) a += em[k] * w[k * HD];
        g_colS[g * HD + c] = a;
    } else if (b < 30) {
        int g = b - 27; float a = 0.f;
        const float* em = col_embs + (l * 3 + g) * 8;
        const float* w = e1 + 552 * HD + c;
#pragma unroll
        for (int k = 0; k < 8; k++) a += em[k] * w[k * HD];
        g_colD[g * HD + c] = a;
    } else if (b < 38) {
        int r = b - 30; float a = n1b[l * HD + c];
        const float* em = role_embs + (l * 8 + r) * 8;
        const float* w = n1 + 512 * HD + c;
#pragma unroll
        for (int k = 0; k < 8; k++) a += em[k] * w[k * HD];
        g_roleN[r * HD + c] = a;
    } else {
        int g = b - 38; float a = 0.f;
        const float* em = col_embs + (l * 3 + g) * 8;
        const float* w = n1 + 520 * HD + c;
#pragma unroll
        for (int k = 0; k < 8; k++) a += em[k] * w[k * HD];
        g_colN[g * HD + c] = a;
    }
}

// A[n, z*256 + c] = h[n] @ e1w[z*256 : z*256+256, :] + role/col tables
__global__ void __launch_bounds__(256) k_gemmA(int l, const float* __restrict__ e1w,
                                               const int* __restrict__ role,
                                               const int* __restrict__ colr) {
    extern __shared__ float sm[];
    float* sA = sm;
    float* sW = sm + 256 * AST;
    int tid = threadIdx.x;
    int tile = blockIdx.x;
    int z = blockIdx.y;
    int r0 = (tid >> 5) * 8;
    int c0 = (tid & 31) * 8;
    int nbase = tile * TIL;

    {   // fill As_t[k][r] = h[n][k]
        int k = tid;
#pragma unroll 4
        for (int r = 0; r < TIL; r++) {
            int n = nbase + r;
            sA[k * AST + r] = (n < NN) ? g_h[n * HD + k] : 0.f;
        }
    }
    const float* gW = e1w + (size_t)l * 560 * HD + (size_t)z * 256 * HD;
    unsigned long long acc[4][8];
#pragma unroll
    for (int p = 0; p < 4; p++)
#pragma unroll
        for (int j = 0; j < 8; j++) acc[p][j] = 0ull;

    for (int kc = 0; kc < HD / KC; kc++) {
        __syncthreads();
        load_w_chunk(sW, gW, kc * KC, tid);
        __syncthreads();
        gemm_chunk(sA, sW, kc * KC, r0, c0, acc);
    }

#pragma unroll
    for (int p = 0; p < 4; p++) {
#pragma unroll
        for (int lh = 0; lh < 2; lh++) {
            int r = r0 + 2 * p + lh;
            int n = nbase + r;
            if (n < NN) {
                const float* tS = (z ? g_roleD : g_roleS) + role[n] * HD + c0;
                const float* tC = (z ? g_colD : g_colS) + colr[n] * HD + c0;
                float v[8];
#pragma unroll
                for (int j = 0; j < 8; j++) {
                    float2 u = unpack2(acc[p][j]);
                    v[j] = (lh ? u.y : u.x) + tS[j] + tC[j];
                }
                float* outp = g_A + n * 512 + z * 256 + c0;
                *(float4*)outp       = make_float4(v[0], v[1], v[2], v[3]);
                *(float4*)(outp + 4) = make_float4(v[4], v[5], v[6], v[7]);
            }
        }
    }
}

__global__ void k_zero() {
    int idx = (blockIdx.x * 256 + threadIdx.x) * 4;
    *(float4*)(g_agg + idx) = make_float4(0.f, 0.f, 0.f, 0.f);
}

// per-edge: m1 = silu(A_src[src]+A_dst[dst]+Trel[rel]); m = silu(m1@e2w+e2b); agg[dst]+=m
__global__ void __launch_bounds__(256) k_edge(int l, const int* __restrict__ ei,
                                              const int* __restrict__ erel,
                                              const float* __restrict__ e2w,
                                              const float* __restrict__ e2b) {
    extern __shared__ float sm[];
    float* sA = sm;
    float* sW = sm + 256 * AST;
    int* s_src = (int*)(sW + KC * HD);
    int* s_dst = s_src + TIL;
    int* s_rel = s_dst + TIL;
    int tid = threadIdx.x;
    int e0 = blockIdx.x * TIL;
    int r0 = (tid >> 5) * 8;
    int c0 = (tid & 31) * 8;

    if (tid < TIL) {
        s_src[tid] = ei[e0 + tid];
        s_dst[tid] = ei[EE + e0 + tid];
        s_rel[tid] = erel[e0 + tid];
    }
    __syncthreads();

    {   // m1 into As_t
        int k = tid;
#pragma unroll 2
        for (int e = 0; e < TIL; e++) {
            float v = __ldg(g_A + s_src[e] * 512 + k)
                    + __ldg(g_A + s_dst[e] * 512 + 256 + k)
                    + g_Trel[s_rel[e] * HD + k];
            sA[k * AST + e] = silu_f(v);
        }
    }

    const float* gW = e2w + (size_t)l * HD * HD;
    unsigned long long acc[4][8];
#pragma unroll
    for (int p = 0; p < 4; p++)
#pragma unroll
        for (int j = 0; j < 8; j++) acc[p][j] = 0ull;

    for (int kc = 0; kc < HD / KC; kc++) {
        __syncthreads();
        load_w_chunk(sW, gW, kc * KC, tid);
        __syncthreads();
        gemm_chunk(sA, sW, kc * KC, r0, c0, acc);
    }

    float bl[8];
#pragma unroll
    for (int j = 0; j < 8; j++) bl[j] = e2b[l * HD + c0 + j];

#pragma unroll
    for (int p = 0; p < 4; p++) {
        int ra = r0 + 2 * p;
        int da = s_dst[ra], db = s_dst[ra + 1];
        float* pa = g_agg + da * HD + c0;
        float* pb = g_agg + db * HD + c0;
#pragma unroll
        for (int j = 0; j < 8; j++) {
            float2 u = unpack2(acc[p][j]);
            atomicAdd(pa + j, silu_f(u.x + bl[j]));
            atomicAdd(pb + j, silu_f(u.y + bl[j]));
        }
    }
}

// node update: u1 = silu([h,agg]@n1w + role/col tabs); x = h + u1@n2w + n2b; h = LN(x)
__global__ void __launch_bounds__(256) k_node(int l, const float* __restrict__ n1w,
                                              const float* __restrict__ n2w,
                                              const float* __restrict__ n2b,
                                              const float* __restrict__ lng,
                                              const float* __restrict__ lnb,
                                              const int* __restrict__ role,
                                              const int* __restrict__ colr) {
    extern __shared__ float sm[];
    float* sA = sm;                     // 512 x AST
    float* sW = sm + 512 * AST;
    float* sU = sA + 256 * AST;         // overlays upper half after GEMM1
    int tid = threadIdx.x;
    int tile = blockIdx.x;
    int r0 = (tid >> 5) * 8;
    int c0 = (tid & 31) * 8;
    int nbase = tile * TIL;

    {   // fill [h ; agg] transposed
        int k = tid;
#pragma unroll 2
        for (int r = 0; r < TIL; r++) {
            int n = nbase + r;
            float hv = 0.f, av = 0.f;
            if (n < NN) { hv = g_h[n * HD + k]; av = g_agg[n * HD + k]; }
            sA[k * AST + r] = hv;
            sA[(256 + k) * AST + r] = av;
        }
    }

    const float* gW1 = n1w + (size_t)l * 528 * HD;
    unsigned long long acc[4][8];
#pragma unroll
    for (int p = 0; p < 4; p++)
#pragma unroll
        for (int j = 0; j < 8; j++) acc[p][j] = 0ull;

    for (int kc = 0; kc < 512 / KC; kc++) {
        __syncthreads();
        load_w_chunk(sW, gW1, kc * KC, tid);
        __syncthreads();
        gemm_chunk(sA, sW, kc * KC, r0, c0, acc);
    }

    __syncthreads();   // all reads of upper As_t done before sU overlay writes
#pragma unroll
    for (int p = 0; p < 4; p++) {
#pragma unroll
        for (int lh = 0; lh < 2; lh++) {
            int r = r0 + 2 * p + lh;
            int n = nbase + r;
            float v[8];
            if (n < NN) {
                const float* tR = g_roleN + role[n] * HD + c0;
                const float* tC = g_colN + colr[n] * HD + c0;
#pragma unroll
                for (int j = 0; j < 8; j++) {
                    float2 u = unpack2(acc[p][j]);
                    v[j] = silu_f((lh ? u.y : u.x) + tR[j] + tC[j]);
                }
            } else {
#pragma unroll
                for (int j = 0; j < 8; j++) v[j] = 0.f;
            }
            float* up = sU + r * 260 + c0;
            *(float4*)up       = make_float4(v[0], v[1], v[2], v[3]);
            *(float4*)(up + 4) = make_float4(v[4], v[5], v[6], v[7]);
        }
    }
    __syncthreads();
    {   // restage u1 transposed into lower As_t
        int k = tid;
#pragma unroll 2
        for (int r = 0; r < TIL; r++) sA[k * AST + r] = sU[r * 260 + k];
    }

    const float* gW2 = n2w + (size_t)l * HD * HD;
#pragma unroll
    for (int p = 0; p < 4; p++)
#pragma unroll
        for (int j = 0; j < 8; j++) acc[p][j] = 0ull;

    for (int kc = 0; kc < HD / KC; kc++) {
        __syncthreads();
        load_w_chunk(sW, gW2, kc * KC, tid);
        __syncthreads();
        gemm_chunk(sA, sW, kc * KC, r0, c0, acc);
    }

    // epilogue: +n2_b, +h residual, LayerNorm, write back h
    float bl[8];
#pragma unroll
    for (int j = 0; j < 8; j++) bl[j] = n2b[l * HD + c0 + j];
    float x[8][8];
#pragma unroll
    for (int p = 0; p < 4; p++)
#pragma unroll
        for (int j = 0; j < 8; j++) {
            float2 u = unpack2(acc[p][j]);
            x[2 * p][j] = u.x;
            x[2 * p + 1][j] = u.y;
        }
#pragma unroll
    for (int i = 0; i < 8; i++) {
        int n = nbase + r0 + i;           // warp-uniform
        if (n < NN) {
            const float* hp = g_h + n * HD + c0;
            float4 h0 = *(const float4*)hp;
            float4 h1 = *(const float4*)(hp + 4);
            x[i][0] += bl[0] + h0.x; x[i][1] += bl[1] + h0.y;
            x[i][2] += bl[2] + h0.z; x[i][3] += bl[3] + h0.w;
            x[i][4] += bl[4] + h1.x; x[i][5] += bl[5] + h1.y;
            x[i][6] += bl[6] + h1.z; x[i][7] += bl[7] + h1.w;
            float s = 0.f, q = 0.f;
#pragma unroll
            for (int j = 0; j < 8; j++) { s += x[i][j]; q += x[i][j] * x[i][j]; }
#pragma unroll
            for (int o = 16; o > 0; o >>= 1) {
                s += __shfl_xor_sync(0xffffffffu, s, o);
                q += __shfl_xor_sync(0xffffffffu, q, o);
            }
            float mu = s * (1.0f / HD);
            float var = q * (1.0f / HD) - mu * mu;
            float rs = rsqrtf(var + 1e-5f);
            float o_[8];
#pragma unroll
            for (int j = 0; j < 8; j++)
                o_[j] = lng[l * HD + c0 + j] * (x[i][j] - mu) * rs + lnb[l * HD + c0 + j];
            float* op = g_h + n * HD + c0;
            *(float4*)op       = make_float4(o_[0], o_[1], o_[2], o_[3]);
            *(float4*)(op + 4) = make_float4(o_[4], o_[5], o_[6], o_[7]);
        }
    }
}

// output head: out = h @ out_w + out_b
__global__ void k_out(const float* __restrict__ ow, const float* __restrict__ ob,
                      float* __restrict__ out) {
    __shared__ float hs[4 * HD];
    int nb = blockIdx.x * 4;
    int tid = threadIdx.x;
    for (int i = tid; i < 4 * HD; i += 256) {
        int n = nb + (i >> 8);
        hs[i] = (n < NN) ? g_h[n * HD + (i & 255)] : 0.f;
    }
    __syncthreads();
    int nl = tid >> 6;
    int c = tid & 63;
    int n = nb + nl;
    float a = ob[c];
    const float* hp = hs + nl * HD;
#pragma unroll 8
    for (int k = 0; k < HD; k++) a += hp[k] * ow[k * 64 + c];
    if (n < NN) out[n * 64 + c] = a;
}

// ---------------- launch ----------------------------------------------------
extern "C" void kernel_launch(void* const* d_in, const int* in_sizes, int n_in,
                              void* d_out, int out_size) {
    const float* scalars   = (const float*)d_in[0];
    const int*   ei        = (const int*)d_in[1];
    const int*   erel      = (const int*)d_in[2];
    const int*   colr      = (const int*)d_in[3];
    const int*   role      = (const int*)d_in[4];
    const float* blk_role  = (const float*)d_in[5];
    const float* blk_col   = (const float*)d_in[6];
    const float* in_w      = (const float*)d_in[7];
    const float* in_b      = (const float*)d_in[8];
    const float* rel_embs  = (const float*)d_in[9];
    const float* role_embs = (const float*)d_in[10];
    const float* col_embs  = (const float*)d_in[11];
    const float* e1_w      = (const float*)d_in[12];
    const float* e1_b      = (const float*)d_in[13];
    const float* e2_w      = (const float*)d_in[14];
    const float* e2_b      = (const float*)d_in[15];
    const float* n1_w      = (const float*)d_in[16];
    const float* n1_b      = (const float*)d_in[17];
    const float* n2_w      = (const float*)d_in[18];
    const float* n2_b      = (const float*)d_in[19];
    const float* ln_g      = (const float*)d_in[20];
    const float* ln_b      = (const float*)d_in[21];
    const float* out_w     = (const float*)d_in[22];
    const float* out_b     = (const float*)d_in[23];
    float* out = (float*)d_out;

    const int SM_A = (256 * AST + KC * HD) * 4;
    const int SM_E = SM_A + 3 * TIL * 4;
    const int SM_N = (512 * AST + KC * HD) * 4;
    cudaFuncSetAttribute(k_gemmA, cudaFuncAttributeMaxDynamicSharedMemorySize, SM_A);
    cudaFuncSetAttribute(k_edge,  cudaFuncAttributeMaxDynamicSharedMemorySize, SM_E);
    cudaFuncSetAttribute(k_node,  cudaFuncAttributeMaxDynamicSharedMemorySize, SM_N);

    int ntiles = (NN + TIL - 1) / TIL;   // 782

    k_input<<<NN, 256>>>(scalars, colr, role, blk_col, blk_role, in_w, in_b);
    for (int l = 0; l < NL; l++) {
        k_tables<<<41, 256>>>(l, rel_embs, role_embs, col_embs, e1_w, e1_b, n1_w, n1_b);
        k_gemmA<<<dim3(ntiles, 2), 256, SM_A>>>(l, e1_w, role, colr);
        k_zero<<<NN * HD / 1024, 256>>>();
        k_edge<<<EE / TIL, 256, SM_E>>>(l, ei, erel, e2_w, e2_b);
        k_node<<<ntiles, 256, SM_N>>>(l, n1_w, n2_w, n2_b, ln_g, ln_b, role, colr);
    }
    k_out<<<NN / 4, 256>>>(out_w, out_b, out);
}

// round 5
// speedup vs baseline: 2.6460x; 2.6460x over previous
#include <cuda_runtime.h>
#include <cuda_fp16.h>
#include <cstdint>

#define NN 50000
#define EE 800000
#define HD 256
#define TIL 64      // rows per SIMT GEMM tile
#define KC  32      // k-chunk staged in smem
#define AST 66      // As_t row stride (floats)
#define NL  3

#define ETIL 128                 // edges per mma tile
#define NTILES_E (EE / ETIL)     // 6250
#define BST 264                  // fp16 smem row stride (halves) for mma tiles

// ---------------- scratch (device globals; no allocation allowed) ----------
__device__ float  g_h[NN * HD];          // node features per layer
__device__ __half g_Ah[NN * 512];        // [A_src | A_dst] per node, fp16
__device__ float  g_agg[NN * HD];        // segment sum (fp32)
__device__ __half g_TrelH[8 * HD];       // rel contribution + e1_b, fp16
__device__ __half g_Bt[HD * HD];         // e2w transposed [n][k] fp16
__device__ float  g_roleS[8 * HD];
__device__ float  g_roleD[8 * HD];
__device__ float  g_colS[3 * HD];
__device__ float  g_colD[3 * HD];
__device__ float  g_roleN[8 * HD];       // includes n1_b
__device__ float  g_colN[3 * HD];

// ---------------- generic helpers -------------------------------------------
__device__ __forceinline__ float silu_f(float x) {
    return __fdividef(x, 1.0f + __expf(-x));
}
__device__ __forceinline__ unsigned long long fma2(unsigned long long a,
                                                   unsigned long long b,
                                                   unsigned long long c) {
    unsigned long long d;
    asm("fma.rn.f32x2 %0, %1, %2, %3;" : "=l"(d) : "l"(a), "l"(b), "l"(c));
    return d;
}
__device__ __forceinline__ unsigned long long pack2(float lo, float hi) {
    unsigned long long d;
    asm("mov.b64 %0, {%1,%2};" : "=l"(d) : "f"(lo), "f"(hi));
    return d;
}
__device__ __forceinline__ float2 unpack2(unsigned long long v) {
    float2 r;
    asm("mov.b64 {%0,%1}, %2;" : "=f"(r.x), "=f"(r.y) : "l"(v));
    return r;
}
__device__ __forceinline__ uint32_t smem_u32(const void* p) {
    uint32_t a;
    asm("{ .reg .u64 t; cvta.to.shared.u64 t, %1; cvt.u32.u64 %0, t; }"
        : "=r"(a) : "l"(p));
    return a;
}

// ---------------- mma.sync helpers (baseline PTX, sm_80+) -------------------
__device__ __forceinline__ void ldsm_x4(uint32_t& r0, uint32_t& r1,
                                        uint32_t& r2, uint32_t& r3, uint32_t addr) {
    asm volatile("ldmatrix.sync.aligned.m8n8.x4.shared.b16 {%0,%1,%2,%3}, [%4];"
                 : "=r"(r0), "=r"(r1), "=r"(r2), "=r"(r3) : "r"(addr));
}
__device__ __forceinline__ void mma16816(float* c, uint32_t a0, uint32_t a1,
                                         uint32_t a2, uint32_t a3,
                                         uint32_t b0, uint32_t b1) {
    asm volatile("mma.sync.aligned.m16n8k16.row.col.f32.f16.f16.f32 "
                 "{%0,%1,%2,%3}, {%4,%5,%6,%7}, {%8,%9}, {%0,%1,%2,%3};"
                 : "+f"(c[0]), "+f"(c[1]), "+f"(c[2]), "+f"(c[3])
                 : "r"(a0), "r"(a1), "r"(a2), "r"(a3), "r"(b0), "r"(b1));
}
__device__ __forceinline__ void red2(float* p, float a, float b) {
    asm volatile("red.global.add.v2.f32 [%0], {%1, %2};"
                 :: "l"(p), "f"(a), "f"(b) : "memory");
}

// ---------------- SIMT GEMM helpers ------------------------------------------
__device__ __forceinline__ void load_w_chunk(float* sW, const float* __restrict__ gW,
                                             int kbase, int tid) {
    const float4* src = (const float4*)(gW + (size_t)kbase * HD);
    float4* dst = (float4*)sW;
#pragma unroll
    for (int i = 0; i < (KC * HD / 4) / 256; i++)
        dst[tid + i * 256] = __ldg(src + tid + i * 256);
}
__device__ __forceinline__ void gemm_chunk(const float* __restrict__ sA,
                                           const float* __restrict__ sW,
                                           int kbase, int r0, int c0,
                                           unsigned long long (&acc)[4][8]) {
#pragma unroll 8
    for (int kk = 0; kk < KC; kk++) {
        const float* ap = sA + (kbase + kk) * AST + r0;
        unsigned long long a0 = *(const unsigned long long*)(ap + 0);
        unsigned long long a1 = *(const unsigned long long*)(ap + 2);
        unsigned long long a2 = *(const unsigned long long*)(ap + 4);
        unsigned long long a3 = *(const unsigned long long*)(ap + 6);
        float4 wa = *(const float4*)(sW + kk * HD + c0);
        float4 wb = *(const float4*)(sW + kk * HD + c0 + 4);
        unsigned long long w2[8];
        w2[0] = pack2(wa.x, wa.x); w2[1] = pack2(wa.y, wa.y);
        w2[2] = pack2(wa.z, wa.z); w2[3] = pack2(wa.w, wa.w);
        w2[4] = pack2(wb.x, wb.x); w2[5] = pack2(wb.y, wb.y);
        w2[6] = pack2(wb.z, wb.z); w2[7] = pack2(wb.w, wb.w);
#pragma unroll
        for (int j = 0; j < 8; j++) {
            acc[0][j] = fma2(a0, w2[j], acc[0][j]);
            acc[1][j] = fma2(a1, w2[j], acc[1][j]);
            acc[2][j] = fma2(a2, w2[j], acc[2][j]);
            acc[3][j] = fma2(a3, w2[j], acc[3][j]);
        }
    }
}

// ---------------- kernels ---------------------------------------------------
__global__ void k_input(const float* __restrict__ sc, const int* __restrict__ colr,
                        const int* __restrict__ role, const float* __restrict__ cemb,
                        const float* __restrict__ remb, const float* __restrict__ inw,
                        const float* __restrict__ inb) {
    __shared__ float xin[32];
    int n = blockIdx.x;
    int tid = threadIdx.x;
    if (tid < 16) xin[tid] = sc[n * 16 + tid];
    else if (tid < 24) xin[tid] = cemb[colr[n] * 8 + (tid - 16)];
    else if (tid < 32) xin[tid] = remb[role[n] * 8 + (tid - 24)];
    __syncthreads();
    float a = inb[tid];
#pragma unroll
    for (int k = 0; k < 32; k++) a += xin[k] * inw[k * HD + tid];
    g_h[n * HD + tid] = a;
}

__global__ void k_tables(int l, const float* __restrict__ rel_embs,
                         const float* __restrict__ role_embs,
                         const float* __restrict__ col_embs,
                         const float* __restrict__ e1w, const float* __restrict__ e1b,
                         const float* __restrict__ n1w, const float* __restrict__ n1b) {
    int b = blockIdx.x, c = threadIdx.x;
    const float* e1 = e1w + (size_t)l * 560 * HD;
    const float* n1 = n1w + (size_t)l * 528 * HD;
    if (b < 8) {
        float a = e1b[l * HD + c];
        const float* em = rel_embs + (l * 8 + b) * 16;
        const float* w = e1 + 512 * HD + c;
#pragma unroll
        for (int k = 0; k < 16; k++) a += em[k] * w[k * HD];
        g_TrelH[b * HD + c] = __float2half(a);
    } else if (b < 16) {
        int r = b - 8; float a = 0.f;
        const float* em = role_embs + (l * 8 + r) * 8;
        const float* w = e1 + 528 * HD + c;
#pragma unroll
        for (int k = 0; k < 8; k++) a += em[k] * w[k * HD];
        g_roleS[r * HD + c] = a;
    } else if (b < 24) {
        int r = b - 16; float a = 0.f;
        const float* em = role_embs + (l * 8 + r) * 8;
        const float* w = e1 + 536 * HD + c;
#pragma unroll
        for (int k = 0; k < 8; k++) a += em[k] * w[k * HD];
        g_roleD[r * HD + c] = a;
    } else if (b < 27) {
        int g = b - 24; float a = 0.f;
        const float* em = col_embs + (l * 3 + g) * 8;
        const float* w = e1 + 544 * HD + c;
#pragma unroll
        for (int k = 0; k < 8; k++) a += em[k] * w[k * HD];
        g_colS[g * HD + c] = a;
    } else if (b < 30) {
        int g = b - 27; float a = 0.f;
        const float* em = col_embs + (l * 3 + g) * 8;
        const float* w = e1 + 552 * HD + c;
#pragma unroll
        for (int k = 0; k < 8; k++) a += em[k] * w[k * HD];
        g_colD[g * HD + c] = a;
    } else if (b < 38) {
        int r = b - 30; float a = n1b[l * HD + c];
        const float* em = role_embs + (l * 8 + r) * 8;
        const float* w = n1 + 512 * HD + c;
#pragma unroll
        for (int k = 0; k < 8; k++) a += em[k] * w[k * HD];
        g_roleN[r * HD + c] = a;
    } else {
        int g = b - 38; float a = 0.f;
        const float* em = col_embs + (l * 3 + g) * 8;
        const float* w = n1 + 520 * HD + c;
#pragma unroll
        for (int k = 0; k < 8; k++) a += em[k] * w[k * HD];
        g_colN[g * HD + c] = a;
    }
}

// transpose e2w[l] -> g_Bt[n][k] fp16
__global__ void k_prepB(int l, const float* __restrict__ e2w) {
    int n = blockIdx.x, k = threadIdx.x;
    g_Bt[n * HD + k] = __float2half(e2w[(size_t)l * HD * HD + k * HD + n]);
}

// A[n, z*256 + c] = h[n] @ e1w[z*256:...] + role/col tables -> fp16 g_Ah
__global__ void __launch_bounds__(256) k_gemmA(int l, const float* __restrict__ e1w,
                                               const int* __restrict__ role,
                                               const int* __restrict__ colr) {
    extern __shared__ float sm[];
    float* sA = sm;
    float* sW = sm + 256 * AST;
    int tid = threadIdx.x;
    int tile = blockIdx.x;
    int z = blockIdx.y;
    int r0 = (tid >> 5) * 8;
    int c0 = (tid & 31) * 8;
    int nbase = tile * TIL;

    {
        int k = tid;
#pragma unroll 4
        for (int r = 0; r < TIL; r++) {
            int n = nbase + r;
            sA[k * AST + r] = (n < NN) ? g_h[n * HD + k] : 0.f;
        }
    }
    const float* gW = e1w + (size_t)l * 560 * HD + (size_t)z * 256 * HD;
    unsigned long long acc[4][8];
#pragma unroll
    for (int p = 0; p < 4; p++)
#pragma unroll
        for (int j = 0; j < 8; j++) acc[p][j] = 0ull;

    for (int kc = 0; kc < HD / KC; kc++) {
        __syncthreads();
        load_w_chunk(sW, gW, kc * KC, tid);
        __syncthreads();
        gemm_chunk(sA, sW, kc * KC, r0, c0, acc);
    }

#pragma unroll
    for (int p = 0; p < 4; p++) {
#pragma unroll
        for (int lh = 0; lh < 2; lh++) {
            int r = r0 + 2 * p + lh;
            int n = nbase + r;
            if (n < NN) {
                const float* tS = (z ? g_roleD : g_roleS) + role[n] * HD + c0;
                const float* tC = (z ? g_colD : g_colS) + colr[n] * HD + c0;
                float v[8];
#pragma unroll
                for (int j = 0; j < 8; j++) {
                    float2 u = unpack2(acc[p][j]);
                    v[j] = (lh ? u.y : u.x) + tS[j] + tC[j];
                }
                __half2* outp = (__half2*)(g_Ah + n * 512 + z * 256 + c0);
#pragma unroll
                for (int j = 0; j < 4; j++)
                    outp[j] = __floats2half2_rn(v[2 * j], v[2 * j + 1]);
            }
        }
    }
}

__global__ void k_zero() {
    int idx = (blockIdx.x * 256 + threadIdx.x) * 4;
    *(float4*)(g_agg + idx) = make_float4(0.f, 0.f, 0.f, 0.f);
}

// ------------- mma.sync edge kernel (persistent) -----------------------------
// smem bytes: [0:1024) bias | [1024:1536) dst | [1536:69120) A fp16 128xBST
//             [69120:204288) B fp16 256xBST
#define EOFF_BIAS 0
#define EOFF_DST  1024
#define EOFF_A    1536
#define EOFF_B    (EOFF_A + ETIL * BST * 2)
#define ESM_TOT   (EOFF_B + HD * BST * 2)

__global__ void __launch_bounds__(256, 1) k_edge_mma(int l, const int* __restrict__ ei,
                                                     const int* __restrict__ erel,
                                                     const float* __restrict__ e2b) {
    extern __shared__ char esm[];
    float* sBias = (float*)(esm + EOFF_BIAS);
    int* sDst = (int*)(esm + EOFF_DST);
    __half* sA = (__half*)(esm + EOFF_A);
    __half* sB = (__half*)(esm + EOFF_B);
    uint32_t sA_u = smem_u32(sA);
    uint32_t sB_u = smem_u32(sB);

    int tid = threadIdx.x;
    int wid = tid >> 5;
    int lane = tid & 31;
    int g = lane >> 2;        // fragment group id
    int tg = lane & 3;
    int mw = wid >> 1;        // warp row quadrant (0..3) -> rows mw*32..+31
    int nw = wid & 1;         // warp col half within pass (0..1) -> 64 cols

    sBias[tid] = e2b[l * HD + tid];
    {   // stage resident B: sB[n][k] = g_Bt[n][k]
        const uint4* src = (const uint4*)(g_Bt + tid * HD);
        uint4* dst = (uint4*)(sB + tid * BST);
#pragma unroll
        for (int i = 0; i < HD / 8; i++) dst[i] = __ldg(src + i);
    }
    __syncthreads();

    // per-lane ldmatrix address components
    int a_row = (lane & 15);
    int a_kof = (lane >> 4) << 3;
    int b_row = ((lane >> 4) << 3) + (lane & 7);
    int b_kof = (lane & 8);

    for (int t = blockIdx.x; t < NTILES_E; t += gridDim.x) {
        int e0 = t * ETIL;
        __syncthreads();                        // prev epilogue done
        if (tid < ETIL) sDst[tid] = ei[EE + e0 + tid];

        // stage A: m1[row][k] = silu(Asrc + Adst + Trel), fp16, row stride BST
#pragma unroll 2
        for (int i = 0; i < 16; i++) {
            int row = wid * 16 + i;
            int src = __ldg(ei + e0 + row);
            int dst = __ldg(ei + EE + e0 + row);
            int rel = __ldg(erel + e0 + row);
            uint4 as4 = *(const uint4*)(g_Ah + (size_t)src * 512 + lane * 8);
            uint4 ad4 = *(const uint4*)(g_Ah + (size_t)dst * 512 + 256 + lane * 8);
            uint4 tr4 = *(const uint4*)(g_TrelH + rel * HD + lane * 8);
            const __half2* pa = (const __half2*)&as4;
            const __half2* pd = (const __half2*)&ad4;
            const __half2* pt = (const __half2*)&tr4;
            uint4 o4;
            __half2* po = (__half2*)&o4;
#pragma unroll
            for (int j = 0; j < 4; j++) {
                float2 fa = __half22float2(pa[j]);
                float2 fb = __half22float2(pd[j]);
                float2 ft = __half22float2(pt[j]);
                po[j] = __floats2half2_rn(silu_f(fa.x + fb.x + ft.x),
                                          silu_f(fa.y + fb.y + ft.y));
            }
            *(uint4*)(sA + row * BST + lane * 8) = o4;
        }
        __syncthreads();

        // two N-passes of 128 cols each
#pragma unroll 1
        for (int p = 0; p < 2; p++) {
            float acc[2][8][4];
#pragma unroll
            for (int i = 0; i < 2; i++)
#pragma unroll
                for (int j = 0; j < 8; j++)
#pragma unroll
                    for (int c = 0; c < 4; c++) acc[i][j][c] = 0.f;

            int cb = p * 128 + nw * 64;         // this warp's col base
#pragma unroll 2
            for (int ks = 0; ks < 16; ks++) {
                int kb = ks * 16;
                uint32_t A0[4], A1[4];
                uint32_t aadr = sA_u + ((mw * 32 + a_row) * BST + kb + a_kof) * 2;
                ldsm_x4(A0[0], A0[1], A0[2], A0[3], aadr);
                ldsm_x4(A1[0], A1[1], A1[2], A1[3], aadr + 16 * BST * 2);
                uint32_t B[8][2];
#pragma unroll
                for (int jj = 0; jj < 4; jj++) {
                    uint32_t badr = sB_u + ((cb + jj * 16 + b_row) * BST + kb + b_kof) * 2;
                    ldsm_x4(B[2 * jj][0], B[2 * jj][1], B[2 * jj + 1][0], B[2 * jj + 1][1], badr);
                }
#pragma unroll
                for (int j = 0; j < 8; j++) {
                    mma16816(acc[0][j], A0[0], A0[1], A0[2], A0[3], B[j][0], B[j][1]);
                    mma16816(acc[1][j], A1[0], A1[1], A1[2], A1[3], B[j][0], B[j][1]);
                }
            }

            // epilogue: bias + silu + scatter-add
#pragma unroll
            for (int i = 0; i < 2; i++) {
                int r1 = mw * 32 + i * 16 + g;
                int r2 = r1 + 8;
                int d1 = sDst[r1];
                int d2 = sDst[r2];
                float* p1 = g_agg + (size_t)d1 * HD;
                float* p2 = g_agg + (size_t)d2 * HD;
#pragma unroll
                for (int j = 0; j < 8; j++) {
                    int col = cb + j * 8 + 2 * tg;
                    float2 bv = *(const float2*)(sBias + col);
                    red2(p1 + col, silu_f(acc[i][j][0] + bv.x), silu_f(acc[i][j][1] + bv.y));
                    red2(p2 + col, silu_f(acc[i][j][2] + bv.x), silu_f(acc[i][j][3] + bv.y));
                }
            }
        }
    }
}

// node update (SIMT)
__global__ void __launch_bounds__(256) k_node(int l, const float* __restrict__ n1w,
                                              const float* __restrict__ n2w,
                                              const float* __restrict__ n2b,
                                              const float* __restrict__ lng,
                                              const float* __restrict__ lnb,
                                              const int* __restrict__ role,
                                              const int* __restrict__ colr) {
    extern __shared__ float sm[];
    float* sA = sm;
    float* sW = sm + 512 * AST;
    float* sU = sA + 256 * AST;
    int tid = threadIdx.x;
    int tile = blockIdx.x;
    int r0 = (tid >> 5) * 8;
    int c0 = (tid & 31) * 8;
    int nbase = tile * TIL;

    {
        int k = tid;
#pragma unroll 2
        for (int r = 0; r < TIL; r++) {
            int n = nbase + r;
            float hv = 0.f, av = 0.f;
            if (n < NN) { hv = g_h[n * HD + k]; av = g_agg[n * HD + k]; }
            sA[k * AST + r] = hv;
            sA[(256 + k) * AST + r] = av;
        }
    }

    const float* gW1 = n1w + (size_t)l * 528 * HD;
    unsigned long long acc[4][8];
#pragma unroll
    for (int p = 0; p < 4; p++)
#pragma unroll
        for (int j = 0; j < 8; j++) acc[p][j] = 0ull;

    for (int kc = 0; kc < 512 / KC; kc++) {
        __syncthreads();
        load_w_chunk(sW, gW1, kc * KC, tid);
        __syncthreads();
        gemm_chunk(sA, sW, kc * KC, r0, c0, acc);
    }

    __syncthreads();
#pragma unroll
    for (int p = 0; p < 4; p++) {
#pragma unroll
        for (int lh = 0; lh < 2; lh++) {
            int r = r0 + 2 * p + lh;
            int n = nbase + r;
            float v[8];
            if (n < NN) {
                const float* tR = g_roleN + role[n] * HD + c0;
                const float* tC = g_colN + colr[n] * HD + c0;
#pragma unroll
                for (int j = 0; j < 8; j++) {
                    float2 u = unpack2(acc[p][j]);
                    v[j] = silu_f((lh ? u.y : u.x) + tR[j] + tC[j]);
                }
            } else {
#pragma unroll
                for (int j = 0; j < 8; j++) v[j] = 0.f;
            }
            float* up = sU + r * 260 + c0;
            *(float4*)up       = make_float4(v[0], v[1], v[2], v[3]);
            *(float4*)(up + 4) = make_float4(v[4], v[5], v[6], v[7]);
        }
    }
    __syncthreads();
    {
        int k = tid;
#pragma unroll 2
        for (int r = 0; r < TIL; r++) sA[k * AST + r] = sU[r * 260 + k];
    }

    const float* gW2 = n2w + (size_t)l * HD * HD;
#pragma unroll
    for (int p = 0; p < 4; p++)
#pragma unroll
        for (int j = 0; j < 8; j++) acc[p][j] = 0ull;

    for (int kc = 0; kc < HD / KC; kc++) {
        __syncthreads();
        load_w_chunk(sW, gW2, kc * KC, tid);
        __syncthreads();
        gemm_chunk(sA, sW, kc * KC, r0, c0, acc);
    }

    float bl[8];
#pragma unroll
    for (int j = 0; j < 8; j++) bl[j] = n2b[l * HD + c0 + j];
    float x[8][8];
#pragma unroll
    for (int p = 0; p < 4; p++)
#pragma unroll
        for (int j = 0; j < 8; j++) {
            float2 u = unpack2(acc[p][j]);
            x[2 * p][j] = u.x;
            x[2 * p + 1][j] = u.y;
        }
#pragma unroll
    for (int i = 0; i < 8; i++) {
        int n = nbase + r0 + i;
        if (n < NN) {
            const float* hp = g_h + n * HD + c0;
            float4 h0 = *(const float4*)hp;
            float4 h1 = *(const float4*)(hp + 4);
            x[i][0] += bl[0] + h0.x; x[i][1] += bl[1] + h0.y;
            x[i][2] += bl[2] + h0.z; x[i][3] += bl[3] + h0.w;
            x[i][4] += bl[4] + h1.x; x[i][5] += bl[5] + h1.y;
            x[i][6] += bl[6] + h1.z; x[i][7] += bl[7] + h1.w;
            float s = 0.f, q = 0.f;
#pragma unroll
            for (int j = 0; j < 8; j++) { s += x[i][j]; q += x[i][j] * x[i][j]; }
#pragma unroll
            for (int o = 16; o > 0; o >>= 1) {
                s += __shfl_xor_sync(0xffffffffu, s, o);
                q += __shfl_xor_sync(0xffffffffu, q, o);
            }
            float mu = s * (1.0f / HD);
            float var = q * (1.0f / HD) - mu * mu;
            float rs = rsqrtf(var + 1e-5f);
            float o_[8];
#pragma unroll
            for (int j = 0; j < 8; j++)
                o_[j] = lng[l * HD + c0 + j] * (x[i][j] - mu) * rs + lnb[l * HD + c0 + j];
            float* op = g_h + n * HD + c0;
            *(float4*)op       = make_float4(o_[0], o_[1], o_[2], o_[3]);
            *(float4*)(op + 4) = make_float4(o_[4], o_[5], o_[6], o_[7]);
        }
    }
}

__global__ void k_out(const float* __restrict__ ow, const float* __restrict__ ob,
                      float* __restrict__ out) {
    __shared__ float hs[4 * HD];
    int nb = blockIdx.x * 4;
    int tid = threadIdx.x;
    for (int i = tid; i < 4 * HD; i += 256) {
        int n = nb + (i >> 8);
        hs[i] = (n < NN) ? g_h[n * HD + (i & 255)] : 0.f;
    }
    __syncthreads();
    int nl = tid >> 6;
    int c = tid & 63;
    int n = nb + nl;
    float a = ob[c];
    const float* hp = hs + nl * HD;
#pragma unroll 8
    for (int k = 0; k < HD; k++) a += hp[k] * ow[k * 64 + c];
    if (n < NN) out[n * 64 + c] = a;
}

// ---------------- launch ----------------------------------------------------
extern "C" void kernel_launch(void* const* d_in, const int* in_sizes, int n_in,
                              void* d_out, int out_size) {
    const float* scalars   = (const float*)d_in[0];
    const int*   ei        = (const int*)d_in[1];
    const int*   erel      = (const int*)d_in[2];
    const int*   colr      = (const int*)d_in[3];
    const int*   role      = (const int*)d_in[4];
    const float* blk_role  = (const float*)d_in[5];
    const float* blk_col   = (const float*)d_in[6];
    const float* in_w      = (const float*)d_in[7];
    const float* in_b      = (const float*)d_in[8];
    const float* rel_embs  = (const float*)d_in[9];
    const float* role_embs = (const float*)d_in[10];
    const float* col_embs  = (const float*)d_in[11];
    const float* e1_w      = (const float*)d_in[12];
    const float* e1_b      = (const float*)d_in[13];
    const float* e2_w      = (const float*)d_in[14];
    const float* e2_b      = (const float*)d_in[15];
    const float* n1_w      = (const float*)d_in[16];
    const float* n1_b      = (const float*)d_in[17];
    const float* n2_w      = (const float*)d_in[18];
    const float* n2_b      = (const float*)d_in[19];
    const float* ln_g      = (const float*)d_in[20];
    const float* ln_b      = (const float*)d_in[21];
    const float* out_w     = (const float*)d_in[22];
    const float* out_b     = (const float*)d_in[23];
    float* out = (float*)d_out;

    const int SM_A = (256 * AST + KC * HD) * 4;
    const int SM_N = (512 * AST + KC * HD) * 4;
    cudaFuncSetAttribute(k_gemmA,    cudaFuncAttributeMaxDynamicSharedMemorySize, SM_A);
    cudaFuncSetAttribute(k_node,     cudaFuncAttributeMaxDynamicSharedMemorySize, SM_N);
    cudaFuncSetAttribute(k_edge_mma, cudaFuncAttributeMaxDynamicSharedMemorySize, ESM_TOT);

    int ntiles = (NN + TIL - 1) / TIL;   // 782

    k_input<<<NN, 256>>>(scalars, colr, role, blk_col, blk_role, in_w, in_b);
    for (int l = 0; l < NL; l++) {
        k_tables<<<41, 256>>>(l, rel_embs, role_embs, col_embs, e1_w, e1_b, n1_w, n1_b);
        k_prepB<<<HD, HD>>>(l, e2_w);
        k_gemmA<<<dim3(ntiles, 2), 256, SM_A>>>(l, e1_w, role, colr);
        k_zero<<<NN * HD / 1024, 256>>>();
        k_edge_mma<<<148, 256, ESM_TOT>>>(l, ei, erel, e2_b);
        k_node<<<ntiles, 256, SM_N>>>(l, n1_w, n2_w, n2_b, ln_g, ln_b, role, colr);
    }
    k_out<<<NN / 4, 256>>>(out_w, out_b, out);
}

// round 7
// speedup vs baseline: 4.0231x; 1.5204x over previous
#include <cuda_runtime.h>
#include <cuda_fp16.h>
#include <cstdint>

#define NN 50000
#define EE 800000
#define HD 256
#define NL  3

#define ETIL 128                 // rows per mma tile
#define NTILES_E (EE / ETIL)     // 6250
#define NT2 ((NN + 127) / 128)   // 391 node tiles
#define BST 264                  // fp16 smem row stride (halves)

// ---------------- scratch (device globals; no allocation allowed) ----------
__device__ float  g_h[NN * HD];          // node features per layer (fp32)
__device__ __half g_Ah[NN * 512];        // [A_src | A_dst] per node, fp16
__device__ float  g_agg[NN * HD];        // segment sum (fp32)
__device__ float  g_tmp[NN * HD];        // fp32 GEMM staging
__device__ __half g_u1[NN * HD];         // node hidden (fp16)
__device__ __half g_TrelH[8 * HD];       // rel contribution + e1_b, fp16
__device__ __half g_BtE[HD * HD];        // e2w^T fp16 (edge)
__device__ __half g_BtA0[HD * HD];       // e1w[0:256]^T
__device__ __half g_BtA1[HD * HD];       // e1w[256:512]^T
__device__ __half g_BtN1a[HD * HD];      // n1w[0:256]^T
__device__ __half g_BtN1b[HD * HD];      // n1w[256:512]^T
__device__ __half g_BtN2[HD * HD];       // n2w^T
__device__ float  g_roleS[8 * HD];
__device__ float  g_roleD[8 * HD];
__device__ float  g_colS[3 * HD];
__device__ float  g_colD[3 * HD];
__device__ float  g_roleN[8 * HD];       // includes n1_b
__device__ float  g_colN[3 * HD];

// ---------------- helpers ----------------------------------------------------
__device__ __forceinline__ float silu_f(float x) {
    return __fdividef(x, 1.0f + __expf(-x));
}
__device__ __forceinline__ uint32_t smem_u32(const void* p) {
    uint32_t a;
    asm("{ .reg .u64 t; cvta.to.shared.u64 t, %1; cvt.u32.u64 %0, t; }"
        : "=r"(a) : "l"(p));
    return a;
}
__device__ __forceinline__ void ldsm_x4(uint32_t& r0, uint32_t& r1,
                                        uint32_t& r2, uint32_t& r3, uint32_t addr) {
    asm volatile("ldmatrix.sync.aligned.m8n8.x4.shared.b16 {%0,%1,%2,%3}, [%4];"
                 : "=r"(r0), "=r"(r1), "=r"(r2), "=r"(r3) : "r"(addr));
}
__device__ __forceinline__ void mma16816(float* c, uint32_t a0, uint32_t a1,
                                         uint32_t a2, uint32_t a3,
                                         uint32_t b0, uint32_t b1) {
    asm volatile("mma.sync.aligned.m16n8k16.row.col.f32.f16.f16.f32 "
                 "{%0,%1,%2,%3}, {%4,%5,%6,%7}, {%8,%9}, {%0,%1,%2,%3};"
                 : "+f"(c[0]), "+f"(c[1]), "+f"(c[2]), "+f"(c[3])
                 : "r"(a0), "r"(a1), "r"(a2), "r"(a3), "r"(b0), "r"(b1));
}
__device__ __forceinline__ void red2v(float* p, float a, float b) {
    asm volatile("red.global.add.v2.f32 [%0], {%1, %2};"
                 :: "l"(p), "f"(a), "f"(b) : "memory");
}

// ---------------- small kernels ----------------------------------------------
__global__ void k_input(const float* __restrict__ sc, const int* __restrict__ colr,
                        const int* __restrict__ role, const float* __restrict__ cemb,
                        const float* __restrict__ remb, const float* __restrict__ inw,
                        const float* __restrict__ inb) {
    __shared__ float xin[32];
    int n = blockIdx.x;
    int tid = threadIdx.x;
    if (tid < 16) xin[tid] = sc[n * 16 + tid];
    else if (tid < 24) xin[tid] = cemb[colr[n] * 8 + (tid - 16)];
    else if (tid < 32) xin[tid] = remb[role[n] * 8 + (tid - 24)];
    __syncthreads();
    float a = inb[tid];
#pragma unroll
    for (int k = 0; k < 32; k++) a += xin[k] * inw[k * HD + tid];
    g_h[n * HD + tid] = a;
}

__global__ void k_tables(int l, const float* __restrict__ rel_embs,
                         const float* __restrict__ role_embs,
                         const float* __restrict__ col_embs,
                         const float* __restrict__ e1w, const float* __restrict__ e1b,
                         const float* __restrict__ n1w, const float* __restrict__ n1b) {
    int b = blockIdx.x, c = threadIdx.x;
    const float* e1 = e1w + (size_t)l * 560 * HD;
    const float* n1 = n1w + (size_t)l * 528 * HD;
    if (b < 8) {
        float a = e1b[l * HD + c];
        const float* em = rel_embs + (l * 8 + b) * 16;
        const float* w = e1 + 512 * HD + c;
#pragma unroll
        for (int k = 0; k < 16; k++) a += em[k] * w[k * HD];
        g_TrelH[b * HD + c] = __float2half(a);
    } else if (b < 16) {
        int r = b - 8; float a = 0.f;
        const float* em = role_embs + (l * 8 + r) * 8;
        const float* w = e1 + 528 * HD + c;
#pragma unroll
        for (int k = 0; k < 8; k++) a += em[k] * w[k * HD];
        g_roleS[r * HD + c] = a;
    } else if (b < 24) {
        int r = b - 16; float a = 0.f;
        const float* em = role_embs + (l * 8 + r) * 8;
        const float* w = e1 + 536 * HD + c;
#pragma unroll
        for (int k = 0; k < 8; k++) a += em[k] * w[k * HD];
        g_roleD[r * HD + c] = a;
    } else if (b < 27) {
        int g = b - 24; float a = 0.f;
        const float* em = col_embs + (l * 3 + g) * 8;
        const float* w = e1 + 544 * HD + c;
#pragma unroll
        for (int k = 0; k < 8; k++) a += em[k] * w[k * HD];
        g_colS[g * HD + c] = a;
    } else if (b < 30) {
        int g = b - 27; float a = 0.f;
        const float* em = col_embs + (l * 3 + g) * 8;
        const float* w = e1 + 552 * HD + c;
#pragma unroll
        for (int k = 0; k < 8; k++) a += em[k] * w[k * HD];
        g_colD[g * HD + c] = a;
    } else if (b < 38) {
        int r = b - 30; float a = n1b[l * HD + c];
        const float* em = role_embs + (l * 8 + r) * 8;
        const float* w = n1 + 512 * HD + c;
#pragma unroll
        for (int k = 0; k < 8; k++) a += em[k] * w[k * HD];
        g_roleN[r * HD + c] = a;
    } else {
        int g = b - 38; float a = 0.f;
        const float* em = col_embs + (l * 3 + g) * 8;
        const float* w = n1 + 520 * HD + c;
#pragma unroll
        for (int k = 0; k < 8; k++) a += em[k] * w[k * HD];
        g_colN[g * HD + c] = a;
    }
}

// transpose+convert the 6 weight matrices for this layer
__global__ void k_prepB(int l, const float* __restrict__ e1w,
                        const float* __restrict__ e2w,
                        const float* __restrict__ n1w,
                        const float* __restrict__ n2w) {
    int n = blockIdx.x, which = blockIdx.y, k = threadIdx.x;
    float v; __half* dst;
    switch (which) {
        case 0: v = e1w[((size_t)l * 560 + k) * HD + n];        dst = g_BtA0;  break;
        case 1: v = e1w[((size_t)l * 560 + 256 + k) * HD + n];  dst = g_BtA1;  break;
        case 2: v = n1w[((size_t)l * 528 + k) * HD + n];        dst = g_BtN1a; break;
        case 3: v = n1w[((size_t)l * 528 + 256 + k) * HD + n];  dst = g_BtN1b; break;
        case 4: v = n2w[((size_t)l * 256 + k) * HD + n];        dst = g_BtN2;  break;
        default: v = e2w[((size_t)l * 256 + k) * HD + n];       dst = g_BtE;   break;
    }
    dst[n * HD + k] = __float2half(v);
}

__global__ void k_zero() {
    int idx = (blockIdx.x * 256 + threadIdx.x) * 4;
    *(float4*)(g_agg + idx) = make_float4(0.f, 0.f, 0.f, 0.f);
}

// ------------- unified persistent mma GEMM (M=50k, N=256, K=256) ------------
// MODE 0: A=g_h,   B=g_BtA0,  epi = +roleS/colS tables     -> g_Ah[:, 0:256]
// MODE 1: A=g_h,   B=g_BtA1,  epi = +roleD/colD tables     -> g_Ah[:, 256:512]
// MODE 2: A=g_h,   B=g_BtN1a, epi = raw fp32               -> g_tmp
// MODE 3: A=g_agg, B=g_BtN1b, epi = +g_tmp +roleN/colN, silu -> g_u1 fp16
// MODE 4: A=g_u1,  B=g_BtN2,  epi = raw fp32               -> g_tmp
#define GOFF_A 0
#define GOFF_B (ETIL * BST * 2)
#define GSM_TOT (GOFF_B + HD * BST * 2)

template <int MODE>
__global__ void __launch_bounds__(256, 1) k_gemm_mma(const int* __restrict__ role,
                                                     const int* __restrict__ colr) {
    // device-side symbol selection (host code must NOT take __device__ addresses)
    const __half* Bt;
    if (MODE == 0) Bt = g_BtA0;
    else if (MODE == 1) Bt = g_BtA1;
    else if (MODE == 2) Bt = g_BtN1a;
    else if (MODE == 3) Bt = g_BtN1b;
    else Bt = g_BtN2;

    extern __shared__ char gsm[];
    __half* sA = (__half*)(gsm + GOFF_A);
    __half* sB = (__half*)(gsm + GOFF_B);
    uint32_t sA_u = smem_u32(sA);
    uint32_t sB_u = smem_u32(sB);

    int tid = threadIdx.x;
    int wid = tid >> 5;
    int lane = tid & 31;
    int g = lane >> 2;
    int tg = lane & 3;
    int mw = wid >> 1;
    int nw = wid & 1;

    {   // stage resident B
        const uint4* src = (const uint4*)(Bt + tid * HD);
        uint4* dst = (uint4*)(sB + tid * BST);
#pragma unroll
        for (int i = 0; i < HD / 8; i++) dst[i] = __ldg(src + i);
    }
    __syncthreads();

    int a_row = (lane & 15);
    int a_kof = (lane >> 4) << 3;
    int b_row = ((lane >> 4) << 3) + (lane & 7);
    int b_kof = (lane & 8);

    for (int t = blockIdx.x; t < NT2; t += gridDim.x) {
        int nbase = t * ETIL;
        __syncthreads();
        // stage A rows
#pragma unroll 2
        for (int i = 0; i < 16; i++) {
            int row = wid * 16 + i;
            int n = nbase + row;
            uint4 o4 = make_uint4(0u, 0u, 0u, 0u);
            if (n < NN) {
                if (MODE == 4) {
                    o4 = *(const uint4*)(g_u1 + (size_t)n * HD + lane * 8);
                } else {
                    const float* ap = (MODE == 3 ? g_agg : g_h) + (size_t)n * HD + lane * 8;
                    float4 f0 = *(const float4*)ap;
                    float4 f1 = *(const float4*)(ap + 4);
                    __half2* po = (__half2*)&o4;
                    po[0] = __floats2half2_rn(f0.x, f0.y);
                    po[1] = __floats2half2_rn(f0.z, f0.w);
                    po[2] = __floats2half2_rn(f1.x, f1.y);
                    po[3] = __floats2half2_rn(f1.z, f1.w);
                }
            }
            *(uint4*)(sA + row * BST + lane * 8) = o4;
        }
        __syncthreads();

#pragma unroll 1
        for (int p = 0; p < 2; p++) {
            float acc[2][8][4];
#pragma unroll
            for (int i = 0; i < 2; i++)
#pragma unroll
                for (int j = 0; j < 8; j++)
#pragma unroll
                    for (int c = 0; c < 4; c++) acc[i][j][c] = 0.f;

            int cb = p * 128 + nw * 64;
#pragma unroll 2
            for (int ks = 0; ks < 16; ks++) {
                int kb = ks * 16;
                uint32_t A0[4], A1[4];
                uint32_t aadr = sA_u + ((mw * 32 + a_row) * BST + kb + a_kof) * 2;
                ldsm_x4(A0[0], A0[1], A0[2], A0[3], aadr);
                ldsm_x4(A1[0], A1[1], A1[2], A1[3], aadr + 16 * BST * 2);
                uint32_t B[8][2];
#pragma unroll
                for (int jj = 0; jj < 4; jj++) {
                    uint32_t badr = sB_u + ((cb + jj * 16 + b_row) * BST + kb + b_kof) * 2;
                    ldsm_x4(B[2 * jj][0], B[2 * jj][1], B[2 * jj + 1][0], B[2 * jj + 1][1], badr);
                }
#pragma unroll
                for (int j = 0; j < 8; j++) {
                    mma16816(acc[0][j], A0[0], A0[1], A0[2], A0[3], B[j][0], B[j][1]);
                    mma16816(acc[1][j], A1[0], A1[1], A1[2], A1[3], B[j][0], B[j][1]);
                }
            }

            // epilogue
#pragma unroll
            for (int i = 0; i < 2; i++) {
#pragma unroll
                for (int hh = 0; hh < 2; hh++) {
                    int r = mw * 32 + i * 16 + g + hh * 8;
                    int n = nbase + r;
                    if (n >= NN) continue;
                    int rl = 0, cl = 0;
                    if (MODE == 0 || MODE == 1 || MODE == 3) {
                        rl = role[n]; cl = colr[n];
                    }
#pragma unroll
                    for (int j = 0; j < 8; j++) {
                        int col = cb + j * 8 + 2 * tg;
                        float v0 = acc[i][j][hh * 2 + 0];
                        float v1 = acc[i][j][hh * 2 + 1];
                        if (MODE == 0 || MODE == 1) {
                            const float* tS = (MODE ? g_roleD : g_roleS) + rl * HD + col;
                            const float* tC = (MODE ? g_colD : g_colS) + cl * HD + col;
                            float2 s2 = *(const float2*)tS;
                            float2 c2 = *(const float2*)tC;
                            __half2 h2 = __floats2half2_rn(v0 + s2.x + c2.x,
                                                           v1 + s2.y + c2.y);
                            *(__half2*)(g_Ah + (size_t)n * 512 + MODE * 256 + col) = h2;
                        } else if (MODE == 2 || MODE == 4) {
                            *(float2*)(g_tmp + (size_t)n * HD + col) = make_float2(v0, v1);
                        } else {  // MODE 3
                            float2 t2 = *(const float2*)(g_tmp + (size_t)n * HD + col);
                            float2 s2 = *(const float2*)(g_roleN + rl * HD + col);
                            float2 c2 = *(const float2*)(g_colN + cl * HD + col);
                            __half2 h2 = __floats2half2_rn(
                                silu_f(v0 + t2.x + s2.x + c2.x),
                                silu_f(v1 + t2.y + s2.y + c2.y));
                            *(__half2*)(g_u1 + (size_t)n * HD + col) = h2;
                        }
                    }
                }
            }
        }
    }
}

// ------------- mma.sync edge kernel (persistent) -----------------------------
#define EOFF_BIAS 0
#define EOFF_DST  1024
#define EOFF_A    1536
#define EOFF_B    (EOFF_A + ETIL * BST * 2)
#define ESM_TOT   (EOFF_B + HD * BST * 2)

__global__ void __launch_bounds__(256, 1) k_edge_mma(int l, const int* __restrict__ ei,
                                                     const int* __restrict__ erel,
                                                     const float* __restrict__ e2b) {
    extern __shared__ char esm[];
    float* sBias = (float*)(esm + EOFF_BIAS);
    int* sDst = (int*)(esm + EOFF_DST);
    __half* sA = (__half*)(esm + EOFF_A);
    __half* sB = (__half*)(esm + EOFF_B);
    uint32_t sA_u = smem_u32(sA);
    uint32_t sB_u = smem_u32(sB);

    int tid = threadIdx.x;
    int wid = tid >> 5;
    int lane = tid & 31;
    int g = lane >> 2;
    int tg = lane & 3;
    int mw = wid >> 1;
    int nw = wid & 1;

    sBias[tid] = e2b[l * HD + tid];
    {
        const uint4* src = (const uint4*)(g_BtE + tid * HD);
        uint4* dst = (uint4*)(sB + tid * BST);
#pragma unroll
        for (int i = 0; i < HD / 8; i++) dst[i] = __ldg(src + i);
    }
    __syncthreads();

    int a_row = (lane & 15);
    int a_kof = (lane >> 4) << 3;
    int b_row = ((lane >> 4) << 3) + (lane & 7);
    int b_kof = (lane & 8);

    for (int t = blockIdx.x; t < NTILES_E; t += gridDim.x) {
        int e0 = t * ETIL;
        __syncthreads();
        if (tid < ETIL) sDst[tid] = ei[EE + e0 + tid];

#pragma unroll 2
        for (int i = 0; i < 16; i++) {
            int row = wid * 16 + i;
            int src = __ldg(ei + e0 + row);
            int dst = __ldg(ei + EE + e0 + row);
            int rel = __ldg(erel + e0 + row);
            uint4 as4 = *(const uint4*)(g_Ah + (size_t)src * 512 + lane * 8);
            uint4 ad4 = *(const uint4*)(g_Ah + (size_t)dst * 512 + 256 + lane * 8);
            uint4 tr4 = *(const uint4*)(g_TrelH + rel * HD + lane * 8);
            const __half2* pa = (const __half2*)&as4;
            const __half2* pd = (const __half2*)&ad4;
            const __half2* pt = (const __half2*)&tr4;
            uint4 o4;
            __half2* po = (__half2*)&o4;
#pragma unroll
            for (int j = 0; j < 4; j++) {
                float2 fa = __half22float2(pa[j]);
                float2 fb = __half22float2(pd[j]);
                float2 ft = __half22float2(pt[j]);
                po[j] = __floats2half2_rn(silu_f(fa.x + fb.x + ft.x),
                                          silu_f(fa.y + fb.y + ft.y));
            }
            *(uint4*)(sA + row * BST + lane * 8) = o4;
        }
        __syncthreads();

#pragma unroll 1
        for (int p = 0; p < 2; p++) {
            float acc[2][8][4];
#pragma unroll
            for (int i = 0; i < 2; i++)
#pragma unroll
                for (int j = 0; j < 8; j++)
#pragma unroll
                    for (int c = 0; c < 4; c++) acc[i][j][c] = 0.f;

            int cb = p * 128 + nw * 64;
#pragma unroll 2
            for (int ks = 0; ks < 16; ks++) {
                int kb = ks * 16;
                uint32_t A0[4], A1[4];
                uint32_t aadr = sA_u + ((mw * 32 + a_row) * BST + kb + a_kof) * 2;
                ldsm_x4(A0[0], A0[1], A0[2], A0[3], aadr);
                ldsm_x4(A1[0], A1[1], A1[2], A1[3], aadr + 16 * BST * 2);
                uint32_t B[8][2];
#pragma unroll
                for (int jj = 0; jj < 4; jj++) {
                    uint32_t badr = sB_u + ((cb + jj * 16 + b_row) * BST + kb + b_kof) * 2;
                    ldsm_x4(B[2 * jj][0], B[2 * jj][1], B[2 * jj + 1][0], B[2 * jj + 1][1], badr);
                }
#pragma unroll
                for (int j = 0; j < 8; j++) {
                    mma16816(acc[0][j], A0[0], A0[1], A0[2], A0[3], B[j][0], B[j][1]);
                    mma16816(acc[1][j], A1[0], A1[1], A1[2], A1[3], B[j][0], B[j][1]);
                }
            }

#pragma unroll
            for (int i = 0; i < 2; i++) {
                int r1 = mw * 32 + i * 16 + g;
                int r2 = r1 + 8;
                int d1 = sDst[r1];
                int d2 = sDst[r2];
                float* p1 = g_agg + (size_t)d1 * HD;
                float* p2 = g_agg + (size_t)d2 * HD;
#pragma unroll
                for (int j = 0; j < 8; j++) {
                    int col = cb + j * 8 + 2 * tg;
                    float2 bv = *(const float2*)(sBias + col);
                    red2v(p1 + col, silu_f(acc[i][j][0] + bv.x), silu_f(acc[i][j][1] + bv.y));
                    red2v(p2 + col, silu_f(acc[i][j][2] + bv.x), silu_f(acc[i][j][3] + bv.y));
                }
            }
        }
    }
}

// residual + bias + LayerNorm: h = LN(h + g_tmp + n2b)
__global__ void k_ln(int l, const float* __restrict__ n2b,
                     const float* __restrict__ lng, const float* __restrict__ lnb) {
    int wid = threadIdx.x >> 5;
    int lane = threadIdx.x & 31;
    int n = blockIdx.x * 8 + wid;
    int c0 = lane * 8;
    const float* hp = g_h + (size_t)n * HD + c0;
    const float* tp = g_tmp + (size_t)n * HD + c0;
    float x[8];
    float4 h0 = *(const float4*)hp;
    float4 h1 = *(const float4*)(hp + 4);
    float4 t0 = *(const float4*)tp;
    float4 t1 = *(const float4*)(tp + 4);
    float4 b0 = *(const float4*)(n2b + l * HD + c0);
    float4 b1 = *(const float4*)(n2b + l * HD + c0 + 4);
    x[0] = h0.x + t0.x + b0.x; x[1] = h0.y + t0.y + b0.y;
    x[2] = h0.z + t0.z + b0.z; x[3] = h0.w + t0.w + b0.w;
    x[4] = h1.x + t1.x + b1.x; x[5] = h1.y + t1.y + b1.y;
    x[6] = h1.z + t1.z + b1.z; x[7] = h1.w + t1.w + b1.w;
    float s = 0.f, q = 0.f;
#pragma unroll
    for (int j = 0; j < 8; j++) { s += x[j]; q += x[j] * x[j]; }
#pragma unroll
    for (int o = 16; o > 0; o >>= 1) {
        s += __shfl_xor_sync(0xffffffffu, s, o);
        q += __shfl_xor_sync(0xffffffffu, q, o);
    }
    float mu = s * (1.0f / HD);
    float var = q * (1.0f / HD) - mu * mu;
    float rs = rsqrtf(var + 1e-5f);
    float4 gg0 = *(const float4*)(lng + l * HD + c0);
    float4 gg1 = *(const float4*)(lng + l * HD + c0 + 4);
    float4 bb0 = *(const float4*)(lnb + l * HD + c0);
    float4 bb1 = *(const float4*)(lnb + l * HD + c0 + 4);
    float o_[8];
    o_[0] = gg0.x * (x[0] - mu) * rs + bb0.x;
    o_[1] = gg0.y * (x[1] - mu) * rs + bb0.y;
    o_[2] = gg0.z * (x[2] - mu) * rs + bb0.z;
    o_[3] = gg0.w * (x[3] - mu) * rs + bb0.w;
    o_[4] = gg1.x * (x[4] - mu) * rs + bb1.x;
    o_[5] = gg1.y * (x[5] - mu) * rs + bb1.y;
    o_[6] = gg1.z * (x[6] - mu) * rs + bb1.z;
    o_[7] = gg1.w * (x[7] - mu) * rs + bb1.w;
    float* op = g_h + (size_t)n * HD + c0;
    *(float4*)op       = make_float4(o_[0], o_[1], o_[2], o_[3]);
    *(float4*)(op + 4) = make_float4(o_[4], o_[5], o_[6], o_[7]);
}

// output head: out = h @ out_w + out_b
__global__ void k_out(const float* __restrict__ ow, const float* __restrict__ ob,
                      float* __restrict__ out) {
    __shared__ float hs[4 * HD];
    int nb = blockIdx.x * 4;
    int tid = threadIdx.x;
    for (int i = tid; i < 4 * HD; i += 256) {
        int n = nb + (i >> 8);
        hs[i] = (n < NN) ? g_h[n * HD + (i & 255)] : 0.f;
    }
    __syncthreads();
    int nl = tid >> 6;
    int c = tid & 63;
    int n = nb + nl;
    float a = ob[c];
    const float* hp = hs + nl * HD;
#pragma unroll 8
    for (int k = 0; k < HD; k++) a += hp[k] * ow[k * 64 + c];
    if (n < NN) out[n * 64 + c] = a;
}

// ---------------- launch ----------------------------------------------------
extern "C" void kernel_launch(void* const* d_in, const int* in_sizes, int n_in,
                              void* d_out, int out_size) {
    const float* scalars   = (const float*)d_in[0];
    const int*   ei        = (const int*)d_in[1];
    const int*   erel      = (const int*)d_in[2];
    const int*   colr      = (const int*)d_in[3];
    const int*   role      = (const int*)d_in[4];
    const float* blk_role  = (const float*)d_in[5];
    const float* blk_col   = (const float*)d_in[6];
    const float* in_w      = (const float*)d_in[7];
    const float* in_b      = (const float*)d_in[8];
    const float* rel_embs  = (const float*)d_in[9];
    const float* role_embs = (const float*)d_in[10];
    const float* col_embs  = (const float*)d_in[11];
    const float* e1_w      = (const float*)d_in[12];
    const float* e1_b      = (const float*)d_in[13];
    const float* e2_w      = (const float*)d_in[14];
    const float* e2_b      = (const float*)d_in[15];
    const float* n1_w      = (const float*)d_in[16];
    const float* n1_b      = (const float*)d_in[17];
    const float* n2_w      = (const float*)d_in[18];
    const float* n2_b      = (const float*)d_in[19];
    const float* ln_g      = (const float*)d_in[20];
    const float* ln_b      = (const float*)d_in[21];
    const float* out_w     = (const float*)d_in[22];
    const float* out_b     = (const float*)d_in[23];
    float* out = (float*)d_out;

    cudaFuncSetAttribute(k_edge_mma,    cudaFuncAttributeMaxDynamicSharedMemorySize, ESM_TOT);
    cudaFuncSetAttribute(k_gemm_mma<0>, cudaFuncAttributeMaxDynamicSharedMemorySize, GSM_TOT);
    cudaFuncSetAttribute(k_gemm_mma<1>, cudaFuncAttributeMaxDynamicSharedMemorySize, GSM_TOT);
    cudaFuncSetAttribute(k_gemm_mma<2>, cudaFuncAttributeMaxDynamicSharedMemorySize, GSM_TOT);
    cudaFuncSetAttribute(k_gemm_mma<3>, cudaFuncAttributeMaxDynamicSharedMemorySize, GSM_TOT);
    cudaFuncSetAttribute(k_gemm_mma<4>, cudaFuncAttributeMaxDynamicSharedMemorySize, GSM_TOT);

    k_input<<<NN, 256>>>(scalars, colr, role, blk_col, blk_role, in_w, in_b);
    for (int l = 0; l < NL; l++) {
        k_tables<<<41, 256>>>(l, rel_embs, role_embs, col_embs, e1_w, e1_b, n1_w, n1_b);
        k_prepB<<<dim3(HD, 6), HD>>>(l, e1_w, e2_w, n1_w, n2_w);
        k_gemm_mma<0><<<148, 256, GSM_TOT>>>(role, colr);
        k_gemm_mma<1><<<148, 256, GSM_TOT>>>(role, colr);
        k_zero<<<NN * HD / 1024, 256>>>();
        k_edge_mma<<<148, 256, ESM_TOT>>>(l, ei, erel, e2_b);
        k_gemm_mma<2><<<148, 256, GSM_TOT>>>(role, colr);
        k_gemm_mma<3><<<148, 256, GSM_TOT>>>(role, colr);
        k_gemm_mma<4><<<148, 256, GSM_TOT>>>(role, colr);
        k_ln<<<NN / 8, 256>>>(l, n2_b, ln_g, ln_b);
    }
    k_out<<<NN / 4, 256>>>(out_w, out_b, out);
}

// round 8
// speedup vs baseline: 5.1193x; 1.2725x over previous
#include <cuda_runtime.h>
#include <cuda_fp16.h>
#include <cstdint>

#define NN 50000
#define EE 800000
#define HD 256
#define NL  3

#define ETIL 128                 // rows per mma tile
#define NTILES_E (EE / ETIL)     // 6250
#define NT2 ((NN + 127) / 128)   // 391 node tiles
#define BST 264                  // fp16 smem row stride (halves)
#define NTHR 512                 // threads per GEMM/edge CTA (16 warps)

// ---------------- scratch (device globals; no allocation allowed) ----------
__device__ float  g_h[NN * HD];          // node features per layer (fp32)
__device__ __half g_Ah[NN * 512];        // [A_src | A_dst] per node, fp16
__device__ float  g_agg[NN * HD];        // segment sum (fp32)
__device__ float  g_tmp[NN * HD];        // fp32 GEMM staging
__device__ __half g_u1[NN * HD];         // node hidden (fp16)
__device__ __half g_TrelH[8 * HD];       // rel contribution + e1_b, fp16
__device__ __half g_BtE[HD * HD];        // e2w^T fp16 (edge)
__device__ __half g_BtA0[HD * HD];       // e1w[0:256]^T
__device__ __half g_BtA1[HD * HD];       // e1w[256:512]^T
__device__ __half g_BtN1a[HD * HD];      // n1w[0:256]^T
__device__ __half g_BtN1b[HD * HD];      // n1w[256:512]^T
__device__ __half g_BtN2[HD * HD];       // n2w^T
__device__ float  g_roleS[8 * HD];
__device__ float  g_roleD[8 * HD];
__device__ float  g_colS[3 * HD];
__device__ float  g_colD[3 * HD];
__device__ float  g_roleN[8 * HD];       // includes n1_b
__device__ float  g_colN[3 * HD];

// ---------------- helpers ----------------------------------------------------
__device__ __forceinline__ float silu_f(float x) {
    return __fdividef(x, 1.0f + __expf(-x));
}
__device__ __forceinline__ uint32_t smem_u32(const void* p) {
    uint32_t a;
    asm("{ .reg .u64 t; cvta.to.shared.u64 t, %1; cvt.u32.u64 %0, t; }"
        : "=r"(a) : "l"(p));
    return a;
}
__device__ __forceinline__ void ldsm_x4(uint32_t& r0, uint32_t& r1,
                                        uint32_t& r2, uint32_t& r3, uint32_t addr) {
    asm volatile("ldmatrix.sync.aligned.m8n8.x4.shared.b16 {%0,%1,%2,%3}, [%4];"
                 : "=r"(r0), "=r"(r1), "=r"(r2), "=r"(r3) : "r"(addr));
}
__device__ __forceinline__ void mma16816(float* c, uint32_t a0, uint32_t a1,
                                         uint32_t a2, uint32_t a3,
                                         uint32_t b0, uint32_t b1) {
    asm volatile("mma.sync.aligned.m16n8k16.row.col.f32.f16.f16.f32 "
                 "{%0,%1,%2,%3}, {%4,%5,%6,%7}, {%8,%9}, {%0,%1,%2,%3};"
                 : "+f"(c[0]), "+f"(c[1]), "+f"(c[2]), "+f"(c[3])
                 : "r"(a0), "r"(a1), "r"(a2), "r"(a3), "r"(b0), "r"(b1));
}
__device__ __forceinline__ void red2v(float* p, float a, float b) {
    asm volatile("red.global.add.v2.f32 [%0], {%1, %2};"
                 :: "l"(p), "f"(a), "f"(b) : "memory");
}

// ---------------- small kernels ----------------------------------------------
__global__ void k_input(const float* __restrict__ sc, const int* __restrict__ colr,
                        const int* __restrict__ role, const float* __restrict__ cemb,
                        const float* __restrict__ remb, const float* __restrict__ inw,
                        const float* __restrict__ inb) {
    __shared__ float xin[32];
    int n = blockIdx.x;
    int tid = threadIdx.x;
    if (tid < 16) xin[tid] = sc[n * 16 + tid];
    else if (tid < 24) xin[tid] = cemb[colr[n] * 8 + (tid - 16)];
    else if (tid < 32) xin[tid] = remb[role[n] * 8 + (tid - 24)];
    __syncthreads();
    float a = inb[tid];
#pragma unroll
    for (int k = 0; k < 32; k++) a += xin[k] * inw[k * HD + tid];
    g_h[n * HD + tid] = a;
}

__global__ void k_tables(int l, const float* __restrict__ rel_embs,
                         const float* __restrict__ role_embs,
                         const float* __restrict__ col_embs,
                         const float* __restrict__ e1w, const float* __restrict__ e1b,
                         const float* __restrict__ n1w, const float* __restrict__ n1b) {
    int b = blockIdx.x, c = threadIdx.x;
    const float* e1 = e1w + (size_t)l * 560 * HD;
    const float* n1 = n1w + (size_t)l * 528 * HD;
    if (b < 8) {
        float a = e1b[l * HD + c];
        const float* em = rel_embs + (l * 8 + b) * 16;
        const float* w = e1 + 512 * HD + c;
#pragma unroll
        for (int k = 0; k < 16; k++) a += em[k] * w[k * HD];
        g_TrelH[b * HD + c] = __float2half(a);
    } else if (b < 16) {
        int r = b - 8; float a = 0.f;
        const float* em = role_embs + (l * 8 + r) * 8;
        const float* w = e1 + 528 * HD + c;
#pragma unroll
        for (int k = 0; k < 8; k++) a += em[k] * w[k * HD];
        g_roleS[r * HD + c] = a;
    } else if (b < 24) {
        int r = b - 16; float a = 0.f;
        const float* em = role_embs + (l * 8 + r) * 8;
        const float* w = e1 + 536 * HD + c;
#pragma unroll
        for (int k = 0; k < 8; k++) a += em[k] * w[k * HD];
        g_roleD[r * HD + c] = a;
    } else if (b < 27) {
        int g = b - 24; float a = 0.f;
        const float* em = col_embs + (l * 3 + g) * 8;
        const float* w = e1 + 544 * HD + c;
#pragma unroll
        for (int k = 0; k < 8; k++) a += em[k] * w[k * HD];
        g_colS[g * HD + c] = a;
    } else if (b < 30) {
        int g = b - 27; float a = 0.f;
        const float* em = col_embs + (l * 3 + g) * 8;
        const float* w = e1 + 552 * HD + c;
#pragma unroll
        for (int k = 0; k < 8; k++) a += em[k] * w[k * HD];
        g_colD[g * HD + c] = a;
    } else if (b < 38) {
        int r = b - 30; float a = n1b[l * HD + c];
        const float* em = role_embs + (l * 8 + r) * 8;
        const float* w = n1 + 512 * HD + c;
#pragma unroll
        for (int k = 0; k < 8; k++) a += em[k] * w[k * HD];
        g_roleN[r * HD + c] = a;
    } else {
        int g = b - 38; float a = 0.f;
        const float* em = col_embs + (l * 3 + g) * 8;
        const float* w = n1 + 520 * HD + c;
#pragma unroll
        for (int k = 0; k < 8; k++) a += em[k] * w[k * HD];
        g_colN[g * HD + c] = a;
    }
}

// transpose+convert the 6 weight matrices for this layer
__global__ void k_prepB(int l, const float* __restrict__ e1w,
                        const float* __restrict__ e2w,
                        const float* __restrict__ n1w,
                        const float* __restrict__ n2w) {
    int n = blockIdx.x, which = blockIdx.y, k = threadIdx.x;
    float v; __half* dst;
    switch (which) {
        case 0: v = e1w[((size_t)l * 560 + k) * HD + n];        dst = g_BtA0;  break;
        case 1: v = e1w[((size_t)l * 560 + 256 + k) * HD + n];  dst = g_BtA1;  break;
        case 2: v = n1w[((size_t)l * 528 + k) * HD + n];        dst = g_BtN1a; break;
        case 3: v = n1w[((size_t)l * 528 + 256 + k) * HD + n];  dst = g_BtN1b; break;
        case 4: v = n2w[((size_t)l * 256 + k) * HD + n];        dst = g_BtN2;  break;
        default: v = e2w[((size_t)l * 256 + k) * HD + n];       dst = g_BtE;   break;
    }
    dst[n * HD + k] = __float2half(v);
}

__global__ void k_zero() {
    int idx = (blockIdx.x * 256 + threadIdx.x) * 4;
    *(float4*)(g_agg + idx) = make_float4(0.f, 0.f, 0.f, 0.f);
}

// ------------- unified persistent mma GEMM (M=50k, N=256, K=256) ------------
// 512 threads, 16 warps: mw=wid&3 (32-row quarter), nw=wid>>2 (64-col quarter)
// MODE 0: A=g_h,   B=g_BtA0,  epi = +roleS/colS tables       -> g_Ah[:, 0:256]
// MODE 1: A=g_h,   B=g_BtA1,  epi = +roleD/colD tables       -> g_Ah[:, 256:512]
// MODE 2: A=g_h,   B=g_BtN1a, epi = raw fp32                 -> g_tmp
// MODE 3: A=g_agg, B=g_BtN1b, epi = +g_tmp +roleN/colN, silu -> g_u1 fp16
// MODE 4: A=g_u1,  B=g_BtN2,  epi = raw fp32                 -> g_tmp
#define GOFF_A 0
#define GOFF_B (ETIL * BST * 2)
#define GSM_TOT (GOFF_B + HD * BST * 2)

template <int MODE>
__global__ void __launch_bounds__(NTHR, 1) k_gemm_mma(const int* __restrict__ role,
                                                      const int* __restrict__ colr) {
    const __half* Bt;
    if (MODE == 0) Bt = g_BtA0;
    else if (MODE == 1) Bt = g_BtA1;
    else if (MODE == 2) Bt = g_BtN1a;
    else if (MODE == 3) Bt = g_BtN1b;
    else Bt = g_BtN2;

    extern __shared__ char gsm[];
    __half* sA = (__half*)(gsm + GOFF_A);
    __half* sB = (__half*)(gsm + GOFF_B);
    uint32_t sA_u = smem_u32(sA);
    uint32_t sB_u = smem_u32(sB);

    int tid = threadIdx.x;
    int wid = tid >> 5;
    int lane = tid & 31;
    int g = lane >> 2;
    int tg = lane & 3;
    int mw = wid & 3;          // row quarter (32 rows)
    int nw = wid >> 2;         // col quarter (64 cols)
    int cb = nw * 64;

    {   // stage resident B: 512 threads, each 2 rows' worth via strided copy
        for (int r = tid; r < HD * 2; r += NTHR) {
            int row = r >> 1, hh = r & 1;
            const uint4* src = (const uint4*)(Bt + row * HD + hh * 128);
            uint4* dst = (uint4*)(sB + row * BST + hh * 128);
#pragma unroll
            for (int i = 0; i < 16; i++) dst[i] = __ldg(src + i);
        }
    }
    __syncthreads();

    int a_row = (lane & 15);
    int a_kof = (lane >> 4) << 3;
    int b_row = ((lane >> 4) << 3) + (lane & 7);
    int b_kof = (lane & 8);

    for (int t = blockIdx.x; t < NT2; t += gridDim.x) {
        int nbase = t * ETIL;
        __syncthreads();
        // stage A rows: 16 warps x 8 rows
#pragma unroll 2
        for (int i = 0; i < 8; i++) {
            int row = wid * 8 + i;
            int n = nbase + row;
            uint4 o4 = make_uint4(0u, 0u, 0u, 0u);
            if (n < NN) {
                if (MODE == 4) {
                    o4 = *(const uint4*)(g_u1 + (size_t)n * HD + lane * 8);
                } else {
                    const float* ap = (MODE == 3 ? g_agg : g_h) + (size_t)n * HD + lane * 8;
                    float4 f0 = *(const float4*)ap;
                    float4 f1 = *(const float4*)(ap + 4);
                    __half2* po = (__half2*)&o4;
                    po[0] = __floats2half2_rn(f0.x, f0.y);
                    po[1] = __floats2half2_rn(f0.z, f0.w);
                    po[2] = __floats2half2_rn(f1.x, f1.y);
                    po[3] = __floats2half2_rn(f1.z, f1.w);
                }
            }
            *(uint4*)(sA + row * BST + lane * 8) = o4;
        }
        __syncthreads();

        float acc[2][8][4];
#pragma unroll
        for (int i = 0; i < 2; i++)
#pragma unroll
            for (int j = 0; j < 8; j++)
#pragma unroll
                for (int c = 0; c < 4; c++) acc[i][j][c] = 0.f;

#pragma unroll 2
        for (int ks = 0; ks < 16; ks++) {
            int kb = ks * 16;
            uint32_t A0[4], A1[4];
            uint32_t aadr = sA_u + ((mw * 32 + a_row) * BST + kb + a_kof) * 2;
            ldsm_x4(A0[0], A0[1], A0[2], A0[3], aadr);
            ldsm_x4(A1[0], A1[1], A1[2], A1[3], aadr + 16 * BST * 2);
            uint32_t B[8][2];
#pragma unroll
            for (int jj = 0; jj < 4; jj++) {
                uint32_t badr = sB_u + ((cb + jj * 16 + b_row) * BST + kb + b_kof) * 2;
                ldsm_x4(B[2 * jj][0], B[2 * jj][1], B[2 * jj + 1][0], B[2 * jj + 1][1], badr);
            }
#pragma unroll
            for (int j = 0; j < 8; j++) {
                mma16816(acc[0][j], A0[0], A0[1], A0[2], A0[3], B[j][0], B[j][1]);
                mma16816(acc[1][j], A1[0], A1[1], A1[2], A1[3], B[j][0], B[j][1]);
            }
        }

        // epilogue
#pragma unroll
        for (int i = 0; i < 2; i++) {
#pragma unroll
            for (int hh = 0; hh < 2; hh++) {
                int r = mw * 32 + i * 16 + g + hh * 8;
                int n = nbase + r;
                if (n >= NN) continue;
                int rl = 0, cl = 0;
                if (MODE == 0 || MODE == 1 || MODE == 3) {
                    rl = role[n]; cl = colr[n];
                }
#pragma unroll
                for (int j = 0; j < 8; j++) {
                    int col = cb + j * 8 + 2 * tg;
                    float v0 = acc[i][j][hh * 2 + 0];
                    float v1 = acc[i][j][hh * 2 + 1];
                    if (MODE == 0 || MODE == 1) {
                        const float* tS = (MODE ? g_roleD : g_roleS) + rl * HD + col;
                        const float* tC = (MODE ? g_colD : g_colS) + cl * HD + col;
                        float2 s2 = *(const float2*)tS;
                        float2 c2 = *(const float2*)tC;
                        __half2 h2 = __floats2half2_rn(v0 + s2.x + c2.x,
                                                       v1 + s2.y + c2.y);
                        *(__half2*)(g_Ah + (size_t)n * 512 + MODE * 256 + col) = h2;
                    } else if (MODE == 2 || MODE == 4) {
                        *(float2*)(g_tmp + (size_t)n * HD + col) = make_float2(v0, v1);
                    } else {  // MODE 3
                        float2 t2 = *(const float2*)(g_tmp + (size_t)n * HD + col);
                        float2 s2 = *(const float2*)(g_roleN + rl * HD + col);
                        float2 c2 = *(const float2*)(g_colN + cl * HD + col);
                        __half2 h2 = __floats2half2_rn(
                            silu_f(v0 + t2.x + s2.x + c2.x),
                            silu_f(v1 + t2.y + s2.y + c2.y));
                        *(__half2*)(g_u1 + (size_t)n * HD + col) = h2;
                    }
                }
            }
        }
    }
}

// ------------- mma.sync edge kernel (persistent, 512 threads) ---------------
#define EOFF_BIAS 0
#define EOFF_DST  1024
#define EOFF_A    1536
#define EOFF_B    (EOFF_A + ETIL * BST * 2)
#define ESM_TOT   (EOFF_B + HD * BST * 2)

__global__ void __launch_bounds__(NTHR, 1) k_edge_mma(int l, const int* __restrict__ ei,
                                                      const int* __restrict__ erel,
                                                      const float* __restrict__ e2b) {
    extern __shared__ char esm[];
    float* sBias = (float*)(esm + EOFF_BIAS);
    int* sDst = (int*)(esm + EOFF_DST);
    __half* sA = (__half*)(esm + EOFF_A);
    __half* sB = (__half*)(esm + EOFF_B);
    uint32_t sA_u = smem_u32(sA);
    uint32_t sB_u = smem_u32(sB);

    int tid = threadIdx.x;
    int wid = tid >> 5;
    int lane = tid & 31;
    int g = lane >> 2;
    int tg = lane & 3;
    int mw = wid & 3;
    int nw = wid >> 2;
    int cb = nw * 64;

    if (tid < HD) sBias[tid] = e2b[l * HD + tid];
    {
        for (int r = tid; r < HD * 2; r += NTHR) {
            int row = r >> 1, hh = r & 1;
            const uint4* src = (const uint4*)(g_BtE + row * HD + hh * 128);
            uint4* dst = (uint4*)(sB + row * BST + hh * 128);
#pragma unroll
            for (int i = 0; i < 16; i++) dst[i] = __ldg(src + i);
        }
    }
    __syncthreads();

    int a_row = (lane & 15);
    int a_kof = (lane >> 4) << 3;
    int b_row = ((lane >> 4) << 3) + (lane & 7);
    int b_kof = (lane & 8);

    for (int t = blockIdx.x; t < NTILES_E; t += gridDim.x) {
        int e0 = t * ETIL;
        __syncthreads();
        if (tid < ETIL) sDst[tid] = ei[EE + e0 + tid];

        // stage A: 16 warps x 8 rows
#pragma unroll 2
        for (int i = 0; i < 8; i++) {
            int row = wid * 8 + i;
            int src = __ldg(ei + e0 + row);
            int dst = __ldg(ei + EE + e0 + row);
            int rel = __ldg(erel + e0 + row);
            uint4 as4 = *(const uint4*)(g_Ah + (size_t)src * 512 + lane * 8);
            uint4 ad4 = *(const uint4*)(g_Ah + (size_t)dst * 512 + 256 + lane * 8);
            uint4 tr4 = *(const uint4*)(g_TrelH + rel * HD + lane * 8);
            const __half2* pa = (const __half2*)&as4;
            const __half2* pd = (const __half2*)&ad4;
            const __half2* pt = (const __half2*)&tr4;
            uint4 o4;
            __half2* po = (__half2*)&o4;
#pragma unroll
            for (int j = 0; j < 4; j++) {
                float2 fa = __half22float2(pa[j]);
                float2 fb = __half22float2(pd[j]);
                float2 ft = __half22float2(pt[j]);
                po[j] = __floats2half2_rn(silu_f(fa.x + fb.x + ft.x),
                                          silu_f(fa.y + fb.y + ft.y));
            }
            *(uint4*)(sA + row * BST + lane * 8) = o4;
        }
        __syncthreads();

        float acc[2][8][4];
#pragma unroll
        for (int i = 0; i < 2; i++)
#pragma unroll
            for (int j = 0; j < 8; j++)
#pragma unroll
                for (int c = 0; c < 4; c++) acc[i][j][c] = 0.f;

#pragma unroll 2
        for (int ks = 0; ks < 16; ks++) {
            int kb = ks * 16;
            uint32_t A0[4], A1[4];
            uint32_t aadr = sA_u + ((mw * 32 + a_row) * BST + kb + a_kof) * 2;
            ldsm_x4(A0[0], A0[1], A0[2], A0[3], aadr);
            ldsm_x4(A1[0], A1[1], A1[2], A1[3], aadr + 16 * BST * 2);
            uint32_t B[8][2];
#pragma unroll
            for (int jj = 0; jj < 4; jj++) {
                uint32_t badr = sB_u + ((cb + jj * 16 + b_row) * BST + kb + b_kof) * 2;
                ldsm_x4(B[2 * jj][0], B[2 * jj][1], B[2 * jj + 1][0], B[2 * jj + 1][1], badr);
            }
#pragma unroll
            for (int j = 0; j < 8; j++) {
                mma16816(acc[0][j], A0[0], A0[1], A0[2], A0[3], B[j][0], B[j][1]);
                mma16816(acc[1][j], A1[0], A1[1], A1[2], A1[3], B[j][0], B[j][1]);
            }
        }

        // epilogue: bias + silu + scatter-add
#pragma unroll
        for (int i = 0; i < 2; i++) {
            int r1 = mw * 32 + i * 16 + g;
            int r2 = r1 + 8;
            int d1 = sDst[r1];
            int d2 = sDst[r2];
            float* p1 = g_agg + (size_t)d1 * HD;
            float* p2 = g_agg + (size_t)d2 * HD;
#pragma unroll
            for (int j = 0; j < 8; j++) {
                int col = cb + j * 8 + 2 * tg;
                float2 bv = *(const float2*)(sBias + col);
                red2v(p1 + col, silu_f(acc[i][j][0] + bv.x), silu_f(acc[i][j][1] + bv.y));
                red2v(p2 + col, silu_f(acc[i][j][2] + bv.x), silu_f(acc[i][j][3] + bv.y));
            }
        }
    }
}

// residual + bias + LayerNorm: h = LN(h + g_tmp + n2b)
__global__ void k_ln(int l, const float* __restrict__ n2b,
                     const float* __restrict__ lng, const float* __restrict__ lnb) {
    int wid = threadIdx.x >> 5;
    int lane = threadIdx.x & 31;
    int n = blockIdx.x * 8 + wid;
    int c0 = lane * 8;
    const float* hp = g_h + (size_t)n * HD + c0;
    const float* tp = g_tmp + (size_t)n * HD + c0;
    float x[8];
    float4 h0 = *(const float4*)hp;
    float4 h1 = *(const float4*)(hp + 4);
    float4 t0 = *(const float4*)tp;
    float4 t1 = *(const float4*)(tp + 4);
    float4 b0 = *(const float4*)(n2b + l * HD + c0);
    float4 b1 = *(const float4*)(n2b + l * HD + c0 + 4);
    x[0] = h0.x + t0.x + b0.x; x[1] = h0.y + t0.y + b0.y;
    x[2] = h0.z + t0.z + b0.z; x[3] = h0.w + t0.w + b0.w;
    x[4] = h1.x + t1.x + b1.x; x[5] = h1.y + t1.y + b1.y;
    x[6] = h1.z + t1.z + b1.z; x[7] = h1.w + t1.w + b1.w;
    float s = 0.f, q = 0.f;
#pragma unroll
    for (int j = 0; j < 8; j++) { s += x[j]; q += x[j] * x[j]; }
#pragma unroll
    for (int o = 16; o > 0; o >>= 1) {
        s += __shfl_xor_sync(0xffffffffu, s, o);
        q += __shfl_xor_sync(0xffffffffu, q, o);
    }
    float mu = s * (1.0f / HD);
    float var = q * (1.0f / HD) - mu * mu;
    float rs = rsqrtf(var + 1e-5f);
    float4 gg0 = *(const float4*)(lng + l * HD + c0);
    float4 gg1 = *(const float4*)(lng + l * HD + c0 + 4);
    float4 bb0 = *(const float4*)(lnb + l * HD + c0);
    float4 bb1 = *(const float4*)(lnb + l * HD + c0 + 4);
    float o_[8];
    o_[0] = gg0.x * (x[0] - mu) * rs + bb0.x;
    o_[1] = gg0.y * (x[1] - mu) * rs + bb0.y;
    o_[2] = gg0.z * (x[2] - mu) * rs + bb0.z;
    o_[3] = gg0.w * (x[3] - mu) * rs + bb0.w;
    o_[4] = gg1.x * (x[4] - mu) * rs + bb1.x;
    o_[5] = gg1.y * (x[5] - mu) * rs + bb1.y;
    o_[6] = gg1.z * (x[6] - mu) * rs + bb1.z;
    o_[7] = gg1.w * (x[7] - mu) * rs + bb1.w;
    float* op = g_h + (size_t)n * HD + c0;
    *(float4*)op       = make_float4(o_[0], o_[1], o_[2], o_[3]);
    *(float4*)(op + 4) = make_float4(o_[4], o_[5], o_[6], o_[7]);
}

// output head: out = h @ out_w + out_b
__global__ void k_out(const float* __restrict__ ow, const float* __restrict__ ob,
                      float* __restrict__ out) {
    __shared__ float hs[4 * HD];
    int nb = blockIdx.x * 4;
    int tid = threadIdx.x;
    for (int i = tid; i < 4 * HD; i += 256) {
        int n = nb + (i >> 8);
        hs[i] = (n < NN) ? g_h[n * HD + (i & 255)] : 0.f;
    }
    __syncthreads();
    int nl = tid >> 6;
    int c = tid & 63;
    int n = nb + nl;
    float a = ob[c];
    const float* hp = hs + nl * HD;
#pragma unroll 8
    for (int k = 0; k < HD; k++) a += hp[k] * ow[k * 64 + c];
    if (n < NN) out[n * 64 + c] = a;
}

// ---------------- launch ----------------------------------------------------
extern "C" void kernel_launch(void* const* d_in, const int* in_sizes, int n_in,
                              void* d_out, int out_size) {
    const float* scalars   = (const float*)d_in[0];
    const int*   ei        = (const int*)d_in[1];
    const int*   erel      = (const int*)d_in[2];
    const int*   colr      = (const int*)d_in[3];
    const int*   role      = (const int*)d_in[4];
    const float* blk_role  = (const float*)d_in[5];
    const float* blk_col   = (const float*)d_in[6];
    const float* in_w      = (const float*)d_in[7];
    const float* in_b      = (const float*)d_in[8];
    const float* rel_embs  = (const float*)d_in[9];
    const float* role_embs = (const float*)d_in[10];
    const float* col_embs  = (const float*)d_in[11];
    const float* e1_w      = (const float*)d_in[12];
    const float* e1_b      = (const float*)d_in[13];
    const float* e2_w      = (const float*)d_in[14];
    const float* e2_b      = (const float*)d_in[15];
    const float* n1_w      = (const float*)d_in[16];
    const float* n1_b      = (const float*)d_in[17];
    const float* n2_w      = (const float*)d_in[18];
    const float* n2_b      = (const float*)d_in[19];
    const float* ln_g      = (const float*)d_in[20];
    const float* ln_b      = (const float*)d_in[21];
    const float* out_w     = (const float*)d_in[22];
    const float* out_b     = (const float*)d_in[23];
    float* out = (float*)d_out;

    cudaFuncSetAttribute(k_edge_mma,    cudaFuncAttributeMaxDynamicSharedMemorySize, ESM_TOT);
    cudaFuncSetAttribute(k_gemm_mma<0>, cudaFuncAttributeMaxDynamicSharedMemorySize, GSM_TOT);
    cudaFuncSetAttribute(k_gemm_mma<1>, cudaFuncAttributeMaxDynamicSharedMemorySize, GSM_TOT);
    cudaFuncSetAttribute(k_gemm_mma<2>, cudaFuncAttributeMaxDynamicSharedMemorySize, GSM_TOT);
    cudaFuncSetAttribute(k_gemm_mma<3>, cudaFuncAttributeMaxDynamicSharedMemorySize, GSM_TOT);
    cudaFuncSetAttribute(k_gemm_mma<4>, cudaFuncAttributeMaxDynamicSharedMemorySize, GSM_TOT);

    k_input<<<NN, 256>>>(scalars, colr, role, blk_col, blk_role, in_w, in_b);
    for (int l = 0; l < NL; l++) {
        k_tables<<<41, 256>>>(l, rel_embs, role_embs, col_embs, e1_w, e1_b, n1_w, n1_b);
        k_prepB<<<dim3(HD, 6), HD>>>(l, e1_w, e2_w, n1_w, n2_w);
        k_gemm_mma<0><<<148, NTHR, GSM_TOT>>>(role, colr);
        k_gemm_mma<1><<<148, NTHR, GSM_TOT>>>(role, colr);
        k_zero<<<NN * HD / 1024, 256>>>();
        k_edge_mma<<<148, NTHR, ESM_TOT>>>(l, ei, erel, e2_b);
        k_gemm_mma<2><<<148, NTHR, GSM_TOT>>>(role, colr);
        k_gemm_mma<3><<<148, NTHR, GSM_TOT>>>(role, colr);
        k_gemm_mma<4><<<148, NTHR, GSM_TOT>>>(role, colr);
        k_ln<<<NN / 8, 256>>>(l, n2_b, ln_g, ln_b);
    }
    k_out<<<NN / 4, 256>>>(out_w, out_b, out);
}